// round 14
// baseline (speedup 1.0000x reference)
#include <cuda_runtime.h>
#include <cuda_fp16.h>
#include <math.h>

// ---------------------------------------------------------------------------
// Problem constants
// ---------------------------------------------------------------------------
#define T_DIM   1024
#define B_DIM   4
#define D_DIM   768
#define H_DIM   12
#define HD_DIM  64
#define FF_DIM  3072
#define NROWS   4096          // T*B
#define NHEADS  48            // B*H
#define ALPHA_C 2.2133638394006434f   // 24^0.25
#define QSCALE  0.00390625f           // 0.125/32
#define KV_SPLIT 2
#define FA_ROWS  49152        // NHEADS * T_DIM

// ---------------------------------------------------------------------------
// Scratch (device globals: allocation-free rule)
// ---------------------------------------------------------------------------
__device__ __half g_hstates[NROWS * D_DIM];
__device__ __half g_hWq[D_DIM * D_DIM];
__device__ __half g_hWk[D_DIM * D_DIM];
__device__ __half g_hWv[D_DIM * D_DIM];
__device__ __half g_hWo[D_DIM * D_DIM];
__device__ __half g_hW1[FF_DIM * D_DIM];
__device__ __half g_hW2[D_DIM * FF_DIM];
__device__ __half g_hq [NHEADS * T_DIM * HD_DIM];
__device__ __half g_hk [NHEADS * T_DIM * HD_DIM];
__device__ __half g_hv [NHEADS * T_DIM * HD_DIM];
__device__ __half g_hctx[NROWS * D_DIM];
__device__ __half g_hx [NROWS * D_DIM];
__device__ __half g_hh [NROWS * FF_DIM];
__device__ float  g_gate[NHEADS * T_DIM];
__device__ float  g_y1 [NROWS * D_DIM];
__device__ float  g_x  [NROWS * D_DIM];
__device__ float  g_y2 [NROWS * D_DIM];
__device__ float2 g_fml[KV_SPLIT * FA_ROWS];            // (m, l) per split/row
__device__ float  g_fao[KV_SPLIT * FA_ROWS * HD_DIM];   // unnormalized O

// ---------------------------------------------------------------------------
// PTX helpers
// ---------------------------------------------------------------------------
__device__ __forceinline__ unsigned sm_u32(const void* p) {
    return (unsigned)__cvta_generic_to_shared(p);
}
__device__ __forceinline__ void cp16(void* s, const void* g) {
    asm volatile("cp.async.ca.shared.global [%0], [%1], 16;\n"
                 :: "r"(sm_u32(s)), "l"(g));
}
#define CP_COMMIT() asm volatile("cp.async.commit_group;\n")
#define CP_WAIT(N)  asm volatile("cp.async.wait_group %0;\n" :: "n"(N))

__device__ __forceinline__ void ldsm_x4(unsigned* f, unsigned addr) {
    asm volatile("ldmatrix.sync.aligned.m8n8.x4.shared.b16 {%0,%1,%2,%3}, [%4];"
                 : "=r"(f[0]), "=r"(f[1]), "=r"(f[2]), "=r"(f[3]) : "r"(addr));
}
__device__ __forceinline__ void ldsm_x4_t(unsigned* f, unsigned addr) {
    asm volatile("ldmatrix.sync.aligned.m8n8.x4.trans.shared.b16 {%0,%1,%2,%3}, [%4];"
                 : "=r"(f[0]), "=r"(f[1]), "=r"(f[2]), "=r"(f[3]) : "r"(addr));
}
__device__ __forceinline__ void mma_fp16(float* d, const unsigned* a,
                                         unsigned b0, unsigned b1) {
    asm volatile(
        "mma.sync.aligned.m16n8k16.row.col.f32.f16.f16.f32 "
        "{%0,%1,%2,%3}, {%4,%5,%6,%7}, {%8,%9}, {%0,%1,%2,%3};\n"
        : "+f"(d[0]), "+f"(d[1]), "+f"(d[2]), "+f"(d[3])
        : "r"(a[0]), "r"(a[1]), "r"(a[2]), "r"(a[3]), "r"(b0), "r"(b1));
}

// ---------------------------------------------------------------------------
// fp32 -> fp16 conversion of states + weights; ALSO emits y1 = states*ALPHA+bo
// ---------------------------------------------------------------------------
__global__ void f2h_all(const float* __restrict__ s0, const float* __restrict__ wq,
                        const float* __restrict__ wk, const float* __restrict__ wv,
                        const float* __restrict__ wo, const float* __restrict__ w1,
                        const float* __restrict__ w2,
                        const float* __restrict__ bo, float* __restrict__ y1)
{
    const int total4 = 2555904;  // 10,223,616 floats / 4
    for (int i = blockIdx.x * blockDim.x + threadIdx.x; i < total4;
         i += gridDim.x * blockDim.x) {
        int f = i * 4;
        const float* src; __half* dst; int off;
        if      (f < 3145728) { src = s0; dst = g_hstates; off = f; }
        else if (f < 3735552) { src = wq; dst = g_hWq; off = f - 3145728; }
        else if (f < 4325376) { src = wk; dst = g_hWk; off = f - 3735552; }
        else if (f < 4915200) { src = wv; dst = g_hWv; off = f - 4325376; }
        else if (f < 5505024) { src = wo; dst = g_hWo; off = f - 4915200; }
        else if (f < 7864320) { src = w1; dst = g_hW1; off = f - 5505024; }
        else                  { src = w2; dst = g_hW2; off = f - 7864320; }
        float4 v = *(const float4*)(src + off);
        half2* d = (half2*)(dst + off);
        d[0] = __floats2half2_rn(v.x, v.y);
        d[1] = __floats2half2_rn(v.z, v.w);
        if (f < 3145728) {   // states chunk: also prefill y1 for Wo split-K
            float4 b = *(const float4*)(bo + (off % D_DIM));
            float4 o;
            o.x = v.x * ALPHA_C + b.x; o.y = v.y * ALPHA_C + b.y;
            o.z = v.z * ALPHA_C + b.z; o.w = v.w * ALPHA_C + b.w;
            *(float4*)(y1 + off) = o;
        }
    }
}

// ---------------------------------------------------------------------------
// fp16 tensor-core GEMM, BK=32, 4-stage cp.async pipeline (1 barrier / 32-k).
// C = A(N x K) @ W(M x K)^T  (+ fused epilogue)
// Split-K via gridDim.z (E_ATOMIC: partials RED.ADD into prefilled C).
// E_QKV fuses the gating computation from raw Q outputs.
// ---------------------------------------------------------------------------
enum { E_QKV = 0, E_ATOMIC = 1, E_GELU = 2 };

#define SROW32 40        // halves per smem row (32 data + 8 pad)
#define MM_STAGES 4
#define STG32  (128 * SROW32)                       // halves per operand/stage
#define MM_SMEM (2 * MM_STAGES * STG32 * 2 + 512)   // bytes (+ wsum)

template <int EPI>
__global__ __launch_bounds__(256, 2) void mm_h(
    const __half* __restrict__ A,
    const __half* __restrict__ W0, const __half* __restrict__ W1h, const __half* __restrict__ W2h,
    const float* __restrict__ bp0, const float* __restrict__ bp1, const float* __restrict__ bp2,
    void* __restrict__ C0, void* __restrict__ C1, void* __restrict__ C2,
    const float* __restrict__ gw, const float* __restrict__ gbb,
    const float* __restrict__ gai, float* __restrict__ gate_out,
    int K, int ldc)
{
    extern __shared__ __half smh[];
    __half* Asm = smh;
    __half* Bsm = smh + MM_STAGES * STG32;
    float*  wsum = (float*)(smh + 2 * MM_STAGES * STG32);

    int sel = 0, mblk = blockIdx.x;
    const __half* W = W0; const float* bias = bp0; void* C = C0;
    if (EPI == E_QKV) {
        sel  = blockIdx.x / 6;
        mblk = blockIdx.x % 6;
        if (sel == 1) { W = W1h; bias = bp1; C = C1; }
        else if (sel == 2) { W = W2h; bias = bp2; C = C2; }
    }

    const int n0 = blockIdx.y * 128;
    const int m0 = mblk * 128;
    const int tid  = threadIdx.x;
    const int lane = tid & 31;
    const int wid  = tid >> 5;
    const int wr = (wid >> 1) * 32;
    const int wc = (wid & 1)  * 64;
    const int g = lane >> 2;
    const int c = lane & 3;

    const int KK   = K / gridDim.z;           // K per split
    const int koff = blockIdx.z * KK;
    const int NK   = KK >> 5;

    if (EPI == E_QKV && sel == 0 && tid < 128) {
        const int hd = tid & 63, base = (tid >> 6) * 256;
        wsum[tid] = gw[base + hd] + gw[base + 64 + hd]
                  + gw[base + 128 + hd] + gw[base + 192 + hd];
    }

    float acc[2][8][4];
#pragma unroll
    for (int mf = 0; mf < 2; mf++)
#pragma unroll
        for (int nf = 0; nf < 8; nf++)
#pragma unroll
            for (int r = 0; r < 4; r++) acc[mf][nf][r] = 0.f;

    const __half* Ab = A + (size_t)n0 * K + koff;
    const __half* Wb = W + (size_t)m0 * K + koff;

    const int lr0 = (tid + 0)   >> 2, ls0 = ((tid + 0)   & 3) * 8;
    const int lr1 = (tid + 256) >> 2, ls1 = ((tid + 256) & 3) * 8;

    // prologue: stages 0..2
#pragma unroll
    for (int s = 0; s < 3; s++) {
        cp16(&Asm[s * STG32 + lr0 * SROW32 + ls0], Ab + (size_t)lr0 * K + s * 32 + ls0);
        cp16(&Asm[s * STG32 + lr1 * SROW32 + ls1], Ab + (size_t)lr1 * K + s * 32 + ls1);
        cp16(&Bsm[s * STG32 + lr0 * SROW32 + ls0], Wb + (size_t)lr0 * K + s * 32 + ls0);
        cp16(&Bsm[s * STG32 + lr1 * SROW32 + ls1], Wb + (size_t)lr1 * K + s * 32 + ls1);
        CP_COMMIT();
    }

    const int a_row = wr + (lane & 15);
    const int a_kb  = (lane >> 4) * 8;
    const int b_row = wc + (lane & 7) + ((lane >> 4) & 1) * 8;
    const int b_kb  = ((lane >> 3) & 1) * 8;

    for (int i = 0; i < NK; i++) {
        const int s   = i % MM_STAGES;
        const int rem = NK - i - 1;
        if      (rem >= 2) CP_WAIT(2);
        else if (rem == 1) CP_WAIT(1);
        else               CP_WAIT(0);
        __syncthreads();

        if (i + 3 < NK) {
            const int s2 = (i + 3) % MM_STAGES;
            const int kt = (i + 3) * 32;
            cp16(&Asm[s2 * STG32 + lr0 * SROW32 + ls0], Ab + (size_t)lr0 * K + kt + ls0);
            cp16(&Asm[s2 * STG32 + lr1 * SROW32 + ls1], Ab + (size_t)lr1 * K + kt + ls1);
            cp16(&Bsm[s2 * STG32 + lr0 * SROW32 + ls0], Wb + (size_t)lr0 * K + kt + ls0);
            cp16(&Bsm[s2 * STG32 + lr1 * SROW32 + ls1], Wb + (size_t)lr1 * K + kt + ls1);
            CP_COMMIT();
        }

#pragma unroll
        for (int kh = 0; kh < 2; kh++) {
            unsigned af[2][4], bf[4][4];
            unsigned abase = sm_u32(&Asm[s * STG32 + a_row * SROW32 + kh * 16 + a_kb]);
            ldsm_x4(af[0], abase);
            ldsm_x4(af[1], abase + 16 * SROW32 * 2);
            unsigned bbase = sm_u32(&Bsm[s * STG32 + b_row * SROW32 + kh * 16 + b_kb]);
#pragma unroll
            for (int bi = 0; bi < 4; bi++)
                ldsm_x4(bf[bi], bbase + bi * 16 * SROW32 * 2);

#pragma unroll
            for (int mf = 0; mf < 2; mf++)
#pragma unroll
                for (int nf = 0; nf < 8; nf++) {
                    const int bi = nf >> 1, hi = (nf & 1) * 2;
                    mma_fp16(acc[mf][nf], af[mf], bf[bi][hi], bf[bi][hi + 1]);
                }
        }
    }

    // gate-path per-thread weights
    float was[16], wbs[16], bsum_a = 0.f, bsum_b = 0.f, gah = 0.f;
    if (EPI == E_QKV && sel == 0) {
#pragma unroll
        for (int nf = 0; nf < 8; nf++) {
            const int hd = (wc + nf * 8 + c * 2) & 63;
            was[nf * 2]     = wsum[hd];
            was[nf * 2 + 1] = wsum[hd + 1];
            wbs[nf * 2]     = wsum[64 + hd];
            wbs[nf * 2 + 1] = wsum[64 + hd + 1];
        }
        bsum_a = gbb[0] + gbb[1] + gbb[2] + gbb[3];
        bsum_b = gbb[4] + gbb[5] + gbb[6] + gbb[7];
        gah = gai[(m0 + wc) >> 6];
    }

    // Epilogue
#pragma unroll
    for (int mf = 0; mf < 2; mf++) {
#pragma unroll
        for (int r2 = 0; r2 < 2; r2++) {
            const int n = n0 + wr + mf * 16 + g + r2 * 8;
            float sa = 0.f, sb = 0.f;
#pragma unroll
            for (int nf = 0; nf < 8; nf++) {
                const int m = m0 + wc + nf * 8 + c * 2;
                if (EPI == E_ATOMIC) {
                    atomicAdd(&((float*)C)[(size_t)n * ldc + m],     acc[mf][nf][r2 * 2]);
                    atomicAdd(&((float*)C)[(size_t)n * ldc + m + 1], acc[mf][nf][r2 * 2 + 1]);
                } else {
                    float v0 = acc[mf][nf][r2 * 2]     + bias[m];
                    float v1 = acc[mf][nf][r2 * 2 + 1] + bias[m + 1];
                    if (EPI == E_QKV) {
                        if (sel == 0) {
                            sa += v0 * was[nf * 2] + v1 * was[nf * 2 + 1];
                            sb += v0 * wbs[nf * 2] + v1 * wbs[nf * 2 + 1];
                            v0 *= QSCALE; v1 *= QSCALE;
                        }
                        const int t = n >> 2, b = n & 3, h = m >> 6, hd = m & 63;
                        *(half2*)&((__half*)C)[(((size_t)(b * H_DIM + h) * T_DIM) + t) * HD_DIM + hd] =
                            __floats2half2_rn(v0, v1);
                    } else { // E_GELU (exact) -> fp16
                        float g0 = 0.5f * v0 * (1.f + erff(v0 * 0.70710678118654752f));
                        float g1 = 0.5f * v1 * (1.f + erff(v1 * 0.70710678118654752f));
                        *(half2*)&((__half*)C)[(size_t)n * ldc + m] = __floats2half2_rn(g0, g1);
                    }
                }
            }
            if (EPI == E_QKV && sel == 0) {
                sa += __shfl_xor_sync(0xffffffffu, sa, 1);
                sa += __shfl_xor_sync(0xffffffffu, sa, 2);
                sb += __shfl_xor_sync(0xffffffffu, sb, 1);
                sb += __shfl_xor_sync(0xffffffffu, sb, 2);
                if (c == 0) {
                    float ga = 1.f / (1.f + __expf(-(sa + bsum_a)));
                    float gb = 1.f / (1.f + __expf(-(sb + bsum_b)));
                    const int t = n >> 2, b = n & 3, h = (m0 + wc) >> 6;
                    gate_out[(b * H_DIM + h) * T_DIM + t] = ga * (gb * gah - 1.f) + 2.f;
                }
            }
        }
    }
}

// ---------------------------------------------------------------------------
// Split-KV tensor-core flash attention + fused pb passthrough copy.
// Grid (8, 48, 2): 128 q-rows/CTA, 8 warps x 16 rows; blockIdx.z = KV half.
// Each CTA handles 8 KV tiles (512 keys) + the matching pb column half.
// Writes UNNORMALIZED O + (m,l) partials; fa_combine merges the halves.
// 3-stage KV ring -> ONE block barrier per tile; pb staged per-warp.
// ---------------------------------------------------------------------------
#define FA_QH   (128 * 72)     // halves
#define FA_KVH  (64 * 72)      // halves per stage
#define FA_NT   8              // KV tiles per split
#define FA_SMEM (FA_QH * 2 + 6 * FA_KVH * 2 + 128 * 72 * 4 + 512)

__global__ __launch_bounds__(256, 2) void flash_attn_h(
    const __half* __restrict__ q, const __half* __restrict__ k,
    const __half* __restrict__ v, const float* __restrict__ pb,
    const float* __restrict__ gate,
    float2* __restrict__ fml, float* __restrict__ fao,
    float* __restrict__ outpb)
{
    extern __shared__ __half smh[];
    __half* Qs  = smh;                        // 128x72 h
    __half* Ks  = smh + FA_QH;                // 3 stages 64x72 h
    __half* Vs  = smh + FA_QH + 3 * FA_KVH;   // 3 stages
    float*  PBs = (float*)(smh + FA_QH + 6 * FA_KVH);   // 128x72 f
    float*  Gs  = PBs + 128 * 72;

    const int bh   = blockIdx.y;
    const int q0   = blockIdx.x * 128;
    const int z    = blockIdx.z;              // KV half
    const int tid  = threadIdx.x;
    const int lane = tid & 31;
    const int w    = tid >> 5;
    const int g    = lane >> 2;
    const int c    = lane & 3;

    const __half* qg = q + ((size_t)bh * T_DIM + q0) * 64;
    const __half* kg = k + (size_t)bh * 65536 + z * (FA_NT * 4096);
    const __half* vg = v + (size_t)bh * 65536 + z * (FA_NT * 4096);
    const float*  pbg = pb + ((size_t)bh * T_DIM + q0) * T_DIM + z * (FA_NT * 64);

    // group 1: Q + KV tile0 (stage 0) + pb tile0 ; group 2: KV tile1 (stage 1)
#pragma unroll
    for (int i = tid; i < 1024; i += 256) {
        int row = i >> 3, ch = (i & 7) * 8;
        cp16(&Qs[row * 72 + ch], qg + row * 64 + ch);
    }
#pragma unroll
    for (int i = tid; i < 512; i += 256) {
        int row = i >> 3, ch = (i & 7) * 8;
        cp16(&Ks[row * 72 + ch], kg + row * 64 + ch);
        cp16(&Vs[row * 72 + ch], vg + row * 64 + ch);
    }
#pragma unroll
    for (int it = 0; it < 8; it++) {
        int cidx = lane + it * 32;
        int row  = w * 16 + (cidx >> 4);
        int chf  = (cidx & 15) * 4;
        cp16(&PBs[row * 72 + chf], pbg + (size_t)row * T_DIM + chf);
    }
    CP_COMMIT();
#pragma unroll
    for (int i = tid; i < 512; i += 256) {
        int row = i >> 3, ch = (i & 7) * 8;
        cp16(&Ks[FA_KVH + row * 72 + ch], kg + 4096 + row * 64 + ch);
        cp16(&Vs[FA_KVH + row * 72 + ch], vg + 4096 + row * 64 + ch);
    }
    CP_COMMIT();
    if (tid < 128) Gs[tid] = gate[bh * T_DIM + q0 + tid];

    CP_WAIT(1);
    __syncthreads();

    // Q fragments (persist in registers)
    unsigned af[4][4];
    {
        const int ar  = w * 16 + (lane & 15);
        const int akb = (lane >> 4) * 8;
#pragma unroll
        for (int ks = 0; ks < 4; ks++)
            ldsm_x4(af[ks], sm_u32(&Qs[ar * 72 + ks * 16 + akb]));
    }

    float m0 = -1e30f, m1 = -1e30f, l0 = 0.f, l1 = 0.f;
    float oacc[8][4];
#pragma unroll
    for (int hb = 0; hb < 8; hb++)
#pragma unroll
        for (int j = 0; j < 4; j++) oacc[hb][j] = 0.f;

    const float gr0 = Gs[w * 16 + g];
    const float gr1 = Gs[w * 16 + g + 8];
    float* opb0 = outpb + ((size_t)bh * T_DIM + q0 + w * 16 + g) * T_DIM + z * (FA_NT * 64);
    float* opb1 = opb0 + 8 * T_DIM;

    const int brow = (lane & 7) + ((lane >> 4) & 1) * 8;
    const int bkb  = ((lane >> 3) & 1) * 8;
    const int vr   = lane & 15;
    const int vcb  = (lane >> 4) * 8;
    const int prow0 = (w * 16 + g) * 72;

    for (int t = 0; t < FA_NT; t++) {
        const int st = t % 3;
        // (1) KV(t) ready. pending allowed: {PB(t), KV(t+1)}  [last: {PB}]
        if (t) {
            if (t < FA_NT - 1) CP_WAIT(2); else CP_WAIT(1);
            __syncthreads();
        }
        // (1b) early prefetch KV(t+2) into stage (t+2)%3
        if (t + 2 < FA_NT) {
            const __half* ks2 = kg + (t + 2) * 4096;
            const __half* vs2 = vg + (t + 2) * 4096;
            __half* kd = Ks + ((t + 2) % 3) * FA_KVH;
            __half* vd = Vs + ((t + 2) % 3) * FA_KVH;
#pragma unroll
            for (int i = tid; i < 512; i += 256) {
                int row = i >> 3, ch = (i & 7) * 8;
                cp16(&kd[row * 72 + ch], ks2 + row * 64 + ch);
                cp16(&vd[row * 72 + ch], vs2 + row * 64 + ch);
            }
            CP_COMMIT();
        }
        const __half* Kb = Ks + st * FA_KVH;
        const __half* Vb = Vs + st * FA_KVH;

        // (2) S = Q @ K^T
        float sacc[8][4];
#pragma unroll
        for (int nb = 0; nb < 8; nb++)
#pragma unroll
            for (int j = 0; j < 4; j++) sacc[nb][j] = 0.f;

#pragma unroll
        for (int nb2 = 0; nb2 < 4; nb2++) {
#pragma unroll
            for (int ks = 0; ks < 4; ks++) {
                unsigned bf[4];
                ldsm_x4(bf, sm_u32(&Kb[(nb2 * 16 + brow) * 72 + ks * 16 + bkb]));
                mma_fp16(sacc[nb2 * 2],     af[ks], bf[0], bf[1]);
                mma_fp16(sacc[nb2 * 2 + 1], af[ks], bf[2], bf[3]);
            }
        }

        // (3) PB(t) ready (warp-local rows). wait(1) only if KV commit happened.
        if (t + 2 < FA_NT) CP_WAIT(1); else CP_WAIT(0);
        __syncwarp();

        // (4) logits + passthrough + online softmax
        float mx0 = -1e30f, mx1 = -1e30f;
#pragma unroll
        for (int nb = 0; nb < 8; nb++) {
            float2 p0 = *(const float2*)&PBs[prow0 + nb * 8 + c * 2];
            float2 p1 = *(const float2*)&PBs[prow0 + 8 * 72 + nb * 8 + c * 2];
            *(float2*)&opb0[t * 64 + nb * 8 + c * 2] = p0;
            *(float2*)&opb1[t * 64 + nb * 8 + c * 2] = p1;
            sacc[nb][0] = 32.f * sacc[nb][0] + gr0 * p0.x;
            sacc[nb][1] = 32.f * sacc[nb][1] + gr0 * p0.y;
            sacc[nb][2] = 32.f * sacc[nb][2] + gr1 * p1.x;
            sacc[nb][3] = 32.f * sacc[nb][3] + gr1 * p1.y;
            mx0 = fmaxf(mx0, fmaxf(sacc[nb][0], sacc[nb][1]));
            mx1 = fmaxf(mx1, fmaxf(sacc[nb][2], sacc[nb][3]));
        }
        mx0 = fmaxf(mx0, __shfl_xor_sync(0xffffffffu, mx0, 1));
        mx0 = fmaxf(mx0, __shfl_xor_sync(0xffffffffu, mx0, 2));
        mx1 = fmaxf(mx1, __shfl_xor_sync(0xffffffffu, mx1, 1));
        mx1 = fmaxf(mx1, __shfl_xor_sync(0xffffffffu, mx1, 2));

        const float nm0 = fmaxf(m0, mx0), nm1 = fmaxf(m1, mx1);
        const float corr0 = __expf(m0 - nm0), corr1 = __expf(m1 - nm1);
        m0 = nm0; m1 = nm1;

        unsigned pa[4][4];
        float s0 = 0.f, s1 = 0.f;
#pragma unroll
        for (int nb = 0; nb < 8; nb++) {
            float e0 = __expf(sacc[nb][0] - nm0);
            float e1 = __expf(sacc[nb][1] - nm0);
            float e2 = __expf(sacc[nb][2] - nm1);
            float e3 = __expf(sacc[nb][3] - nm1);
            s0 += e0 + e1; s1 += e2 + e3;
            const int kp = nb >> 1, off = (nb & 1) * 2;
            half2 h0 = __floats2half2_rn(e0, e1);
            half2 h1 = __floats2half2_rn(e2, e3);
            pa[kp][off]     = *(unsigned*)&h0;
            pa[kp][off + 1] = *(unsigned*)&h1;
        }
        s0 += __shfl_xor_sync(0xffffffffu, s0, 1);
        s0 += __shfl_xor_sync(0xffffffffu, s0, 2);
        s1 += __shfl_xor_sync(0xffffffffu, s1, 1);
        s1 += __shfl_xor_sync(0xffffffffu, s1, 2);
        l0 = l0 * corr0 + s0;
        l1 = l1 * corr1 + s1;

#pragma unroll
        for (int hb = 0; hb < 8; hb++) {
            oacc[hb][0] *= corr0; oacc[hb][1] *= corr0;
            oacc[hb][2] *= corr1; oacc[hb][3] *= corr1;
        }

        // (5) warp done reading its PB rows -> warp-local prefetch of pb(t+1)
        __syncwarp();
        if (t + 1 < FA_NT) {
#pragma unroll
            for (int it = 0; it < 8; it++) {
                int cidx = lane + it * 32;
                int row  = w * 16 + (cidx >> 4);
                int chf  = (cidx & 15) * 4;
                cp16(&PBs[row * 72 + chf],
                     pbg + (size_t)row * T_DIM + (t + 1) * 64 + chf);
            }
            CP_COMMIT();
        }

        // (6) out += P @ V   (V loaded transposed); no bottom barrier needed
#pragma unroll
        for (int kp = 0; kp < 4; kp++) {
#pragma unroll
            for (int hb2 = 0; hb2 < 4; hb2++) {
                unsigned bv[4];
                ldsm_x4_t(bv, sm_u32(&Vb[(kp * 16 + vr) * 72 + hb2 * 16 + vcb]));
                mma_fp16(oacc[hb2 * 2],     pa[kp], bv[0], bv[1]);
                mma_fp16(oacc[hb2 * 2 + 1], pa[kp], bv[2], bv[3]);
            }
        }
    }

    // write partials: (m,l) + unnormalized O
    const int row0 = bh * T_DIM + q0 + w * 16 + g;       // global fa row
    const size_t pbase = (size_t)z * FA_ROWS;
    if (c == 0) {
        fml[pbase + row0]     = make_float2(m0, l0);
        fml[pbase + row0 + 8] = make_float2(m1, l1);
    }
    float* o0 = fao + (pbase + row0) * HD_DIM;
    float* o1 = fao + (pbase + row0 + 8) * HD_DIM;
#pragma unroll
    for (int hb = 0; hb < 8; hb++) {
        const int col = hb * 8 + c * 2;
        *(float2*)&o0[col] = make_float2(oacc[hb][0], oacc[hb][1]);
        *(float2*)&o1[col] = make_float2(oacc[hb][2], oacc[hb][3]);
    }
}

// ---------------------------------------------------------------------------
// Combine the two KV-split halves: exact softmax merge -> hctx (fp16, T,B,D)
// One warp per (bh, t) row. grid 6144 x 256.
// ---------------------------------------------------------------------------
__global__ void fa_combine(const float2* __restrict__ fml,
                           const float* __restrict__ fao,
                           __half* __restrict__ ctx)
{
    const int warp = (blockIdx.x * blockDim.x + threadIdx.x) >> 5;  // 0..49151
    const int lane = threadIdx.x & 31;
    const int bh = warp >> 10, t = warp & 1023;

    const float2 a = fml[warp];
    const float2 b = fml[FA_ROWS + warp];
    const float m  = fmaxf(a.x, b.x);
    const float e0 = __expf(a.x - m), e1 = __expf(b.x - m);
    const float inv = 1.f / (a.y * e0 + b.y * e1);

    const float2 v0 = ((const float2*)(fao + (size_t)warp * HD_DIM))[lane];
    const float2 v1 = ((const float2*)(fao + (size_t)(FA_ROWS + warp) * HD_DIM))[lane];

    const int bb = bh / H_DIM, h = bh % H_DIM;
    __half* dst = ctx + ((size_t)(t * B_DIM + bb)) * D_DIM + h * 64;
    *(half2*)&dst[lane * 2] = __floats2half2_rn(
        (v0.x * e0 + v1.x * e1) * inv,
        (v0.y * e0 + v1.y * e1) * inv);
}

// ---------------------------------------------------------------------------
// LayerNorm (optionally emits fp16 copy and/or y2pre = r*ALPHA + b2)
// ---------------------------------------------------------------------------
__global__ void layernorm_kernel(const float* __restrict__ in,
                                 const float* __restrict__ g,
                                 const float* __restrict__ b,
                                 float* __restrict__ out,
                                 __half* __restrict__ hout,
                                 const float* __restrict__ rb2,
                                 float* __restrict__ y2o)
{
    const int row = blockIdx.x, tid = threadIdx.x;
    const float* xr = in + (size_t)row * D_DIM;
    float v0 = xr[tid], v1 = xr[tid + 256], v2 = xr[tid + 512];
    float s  = v0 + v1 + v2;
    float sq = v0 * v0 + v1 * v1 + v2 * v2;
#pragma unroll
    for (int o = 16; o; o >>= 1) {
        s  += __shfl_xor_sync(0xffffffffu, s,  o);
        sq += __shfl_xor_sync(0xffffffffu, sq, o);
    }
    __shared__ float ss[8], sqs[8], stats[2];
    const int w = tid >> 5, lane = tid & 31;
    if (lane == 0) { ss[w] = s; sqs[w] = sq; }
    __syncthreads();
    if (tid == 0) {
        float S = 0.f, SQ = 0.f;
        for (int i = 0; i < 8; i++) { S += ss[i]; SQ += sqs[i]; }
        float mu  = S * (1.f / 768.f);
        float var = SQ * (1.f / 768.f) - mu * mu;
        stats[0] = mu;
        stats[1] = rsqrtf(var + 1e-5f);
    }
    __syncthreads();
    const float mu = stats[0], rstd = stats[1];
    float r0 = (v0 - mu) * rstd * g[tid]       + b[tid];
    float r1 = (v1 - mu) * rstd * g[tid + 256] + b[tid + 256];
    float r2 = (v2 - mu) * rstd * g[tid + 512] + b[tid + 512];
    float* orow = out + (size_t)row * D_DIM;
    orow[tid] = r0; orow[tid + 256] = r1; orow[tid + 512] = r2;
    if (hout) {
        __half* hrow = hout + (size_t)row * D_DIM;
        hrow[tid] = __float2half_rn(r0);
        hrow[tid + 256] = __float2half_rn(r1);
        hrow[tid + 512] = __float2half_rn(r2);
    }
    if (y2o) {   // prefill for FFN2 split-K: y2 = x*ALPHA + b2
        float* yr = y2o + (size_t)row * D_DIM;
        yr[tid]       = r0 * ALPHA_C + rb2[tid];
        yr[tid + 256] = r1 * ALPHA_C + rb2[tid + 256];
        yr[tid + 512] = r2 * ALPHA_C + rb2[tid + 512];
    }
}

// ---------------------------------------------------------------------------
// Launch
// ---------------------------------------------------------------------------
extern "C" void kernel_launch(void* const* d_in, const int* in_sizes, int n_in,
                              void* d_out, int out_size)
{
    const float* states = (const float*)d_in[0];
    const float* pb     = (const float*)d_in[1];
    const float* Wq = (const float*)d_in[2];   const float* bq = (const float*)d_in[3];
    const float* Wk = (const float*)d_in[4];   const float* bk = (const float*)d_in[5];
    const float* Wv = (const float*)d_in[6];   const float* bv = (const float*)d_in[7];
    const float* Wo = (const float*)d_in[8];   const float* bo = (const float*)d_in[9];
    const float* grep_w = (const float*)d_in[10];
    const float* grep_b = (const float*)d_in[11];
    const float* grep_a = (const float*)d_in[12];
    const float* ln1_g  = (const float*)d_in[13];
    const float* ln1_b  = (const float*)d_in[14];
    const float* W1 = (const float*)d_in[15];  const float* b1 = (const float*)d_in[16];
    const float* W2 = (const float*)d_in[17];  const float* b2 = (const float*)d_in[18];
    const float* ln2_g  = (const float*)d_in[19];
    const float* ln2_b  = (const float*)d_in[20];
    float* out = (float*)d_out;

    __half *hstates, *hWq, *hWk, *hWv, *hWo, *hW1, *hW2;
    __half *hq, *hk, *hv, *hctx, *hx, *hh;
    float  *gate, *y1, *x, *y2, *fao;
    float2 *fml;
    cudaGetSymbolAddress((void**)&hstates, g_hstates);
    cudaGetSymbolAddress((void**)&hWq, g_hWq);
    cudaGetSymbolAddress((void**)&hWk, g_hWk);
    cudaGetSymbolAddress((void**)&hWv, g_hWv);
    cudaGetSymbolAddress((void**)&hWo, g_hWo);
    cudaGetSymbolAddress((void**)&hW1, g_hW1);
    cudaGetSymbolAddress((void**)&hW2, g_hW2);
    cudaGetSymbolAddress((void**)&hq,  g_hq);
    cudaGetSymbolAddress((void**)&hk,  g_hk);
    cudaGetSymbolAddress((void**)&hv,  g_hv);
    cudaGetSymbolAddress((void**)&hctx, g_hctx);
    cudaGetSymbolAddress((void**)&hx,  g_hx);
    cudaGetSymbolAddress((void**)&hh,  g_hh);
    cudaGetSymbolAddress((void**)&gate, g_gate);
    cudaGetSymbolAddress((void**)&y1,  g_y1);
    cudaGetSymbolAddress((void**)&x,   g_x);
    cudaGetSymbolAddress((void**)&y2,  g_y2);
    cudaGetSymbolAddress((void**)&fml, g_fml);
    cudaGetSymbolAddress((void**)&fao, g_fao);

    cudaFuncSetAttribute(mm_h<E_QKV>,    cudaFuncAttributeMaxDynamicSharedMemorySize, MM_SMEM);
    cudaFuncSetAttribute(mm_h<E_ATOMIC>, cudaFuncAttributeMaxDynamicSharedMemorySize, MM_SMEM);
    cudaFuncSetAttribute(mm_h<E_GELU>,   cudaFuncAttributeMaxDynamicSharedMemorySize, MM_SMEM);
    cudaFuncSetAttribute(flash_attn_h,   cudaFuncAttributeMaxDynamicSharedMemorySize, FA_SMEM);

    const dim3 blk(256);

    // fp32 -> fp16 for states + weights ; also prefills y1 = states*ALPHA + bo
    f2h_all<<<2496, blk>>>(states, Wq, Wk, Wv, Wo, W1, W2, bo, y1);

    // Fused QKV projections + gate computation (fp16 tensor cores)
    mm_h<E_QKV><<<dim3(18, 32, 1), blk, MM_SMEM>>>(
        hstates, hWq, hWk, hWv, bq, bk, bv, hq, hk, hv,
        grep_w, grep_b, grep_a, gate, D_DIM, 0);

    // split-KV flash attention (+ fused pb passthrough into out), then combine
    flash_attn_h<<<dim3(T_DIM / 128, NHEADS, KV_SPLIT), blk, FA_SMEM>>>(
        hq, hk, hv, pb, gate, fml, fao, out + (size_t)NROWS * D_DIM);
    fa_combine<<<FA_ROWS / 8, blk>>>(fml, fao, hctx);

    // Wo projection: split-K2 atomic GEMM into prefilled y1, then LN1 (+y2 prefill)
    mm_h<E_ATOMIC><<<dim3(6, 32, 2), blk, MM_SMEM>>>(
        hctx, hWo, nullptr, nullptr, nullptr, nullptr, nullptr,
        y1, nullptr, nullptr,
        nullptr, nullptr, nullptr, nullptr, D_DIM, D_DIM);
    layernorm_kernel<<<NROWS, blk>>>(y1, ln1_g, ln1_b, x, hx, b2, y2);

    // FFN
    mm_h<E_GELU><<<dim3(24, 32, 1), blk, MM_SMEM>>>(
        hx, hW1, nullptr, nullptr, b1, nullptr, nullptr,
        hh, nullptr, nullptr,
        nullptr, nullptr, nullptr, nullptr, D_DIM, FF_DIM);
    mm_h<E_ATOMIC><<<dim3(6, 32, 2), blk, MM_SMEM>>>(
        hh, hW2, nullptr, nullptr, nullptr, nullptr, nullptr,
        y2, nullptr, nullptr,
        nullptr, nullptr, nullptr, nullptr, FF_DIM, D_DIM);
    layernorm_kernel<<<NROWS, blk>>>(y2, ln2_g, ln2_b, out, nullptr, nullptr, nullptr);
}

// round 15
// speedup vs baseline: 1.0205x; 1.0205x over previous
#include <cuda_runtime.h>
#include <cuda_fp16.h>
#include <math.h>

// ---------------------------------------------------------------------------
// Problem constants
// ---------------------------------------------------------------------------
#define T_DIM   1024
#define B_DIM   4
#define D_DIM   768
#define H_DIM   12
#define HD_DIM  64
#define FF_DIM  3072
#define NROWS   4096          // T*B
#define NHEADS  48            // B*H
#define ALPHA_C 2.2133638394006434f   // 24^0.25
#define QSCALE  0.00390625f           // 0.125/32

// ---------------------------------------------------------------------------
// Scratch (device globals: allocation-free rule)
// ---------------------------------------------------------------------------
__device__ __half g_hstates[NROWS * D_DIM];
__device__ __half g_hWq[D_DIM * D_DIM];
__device__ __half g_hWk[D_DIM * D_DIM];
__device__ __half g_hWv[D_DIM * D_DIM];
__device__ __half g_hWo[D_DIM * D_DIM];
__device__ __half g_hW1[FF_DIM * D_DIM];
__device__ __half g_hW2[D_DIM * FF_DIM];
__device__ __half g_hq [NHEADS * T_DIM * HD_DIM];
__device__ __half g_hk [NHEADS * T_DIM * HD_DIM];
__device__ __half g_hv [NHEADS * T_DIM * HD_DIM];
__device__ __half g_hctx[NROWS * D_DIM];
__device__ __half g_hx [NROWS * D_DIM];
__device__ __half g_hh [NROWS * FF_DIM];
__device__ float  g_gate[NHEADS * T_DIM];
__device__ float  g_y1 [NROWS * D_DIM];
__device__ float  g_x  [NROWS * D_DIM];
__device__ float  g_y2 [NROWS * D_DIM];

// ---------------------------------------------------------------------------
// PTX helpers
// ---------------------------------------------------------------------------
__device__ __forceinline__ unsigned sm_u32(const void* p) {
    return (unsigned)__cvta_generic_to_shared(p);
}
__device__ __forceinline__ void cp16(void* s, const void* g) {
    asm volatile("cp.async.ca.shared.global [%0], [%1], 16;\n"
                 :: "r"(sm_u32(s)), "l"(g));
}
#define CP_COMMIT() asm volatile("cp.async.commit_group;\n")
#define CP_WAIT(N)  asm volatile("cp.async.wait_group %0;\n" :: "n"(N))

__device__ __forceinline__ void ldsm_x4(unsigned* f, unsigned addr) {
    asm volatile("ldmatrix.sync.aligned.m8n8.x4.shared.b16 {%0,%1,%2,%3}, [%4];"
                 : "=r"(f[0]), "=r"(f[1]), "=r"(f[2]), "=r"(f[3]) : "r"(addr));
}
__device__ __forceinline__ void ldsm_x4_t(unsigned* f, unsigned addr) {
    asm volatile("ldmatrix.sync.aligned.m8n8.x4.trans.shared.b16 {%0,%1,%2,%3}, [%4];"
                 : "=r"(f[0]), "=r"(f[1]), "=r"(f[2]), "=r"(f[3]) : "r"(addr));
}
__device__ __forceinline__ void mma_fp16(float* d, const unsigned* a,
                                         unsigned b0, unsigned b1) {
    asm volatile(
        "mma.sync.aligned.m16n8k16.row.col.f32.f16.f16.f32 "
        "{%0,%1,%2,%3}, {%4,%5,%6,%7}, {%8,%9}, {%0,%1,%2,%3};\n"
        : "+f"(d[0]), "+f"(d[1]), "+f"(d[2]), "+f"(d[3])
        : "r"(a[0]), "r"(a[1]), "r"(a[2]), "r"(a[3]), "r"(b0), "r"(b1));
}

// ---------------------------------------------------------------------------
// fp32 -> fp16 conversion of states + weights; ALSO emits y1 = states*ALPHA+bo
// ---------------------------------------------------------------------------
__global__ void f2h_all(const float* __restrict__ s0, const float* __restrict__ wq,
                        const float* __restrict__ wk, const float* __restrict__ wv,
                        const float* __restrict__ wo, const float* __restrict__ w1,
                        const float* __restrict__ w2,
                        const float* __restrict__ bo, float* __restrict__ y1)
{
    const int total4 = 2555904;  // 10,223,616 floats / 4
    for (int i = blockIdx.x * blockDim.x + threadIdx.x; i < total4;
         i += gridDim.x * blockDim.x) {
        int f = i * 4;
        const float* src; __half* dst; int off;
        if      (f < 3145728) { src = s0; dst = g_hstates; off = f; }
        else if (f < 3735552) { src = wq; dst = g_hWq; off = f - 3145728; }
        else if (f < 4325376) { src = wk; dst = g_hWk; off = f - 3735552; }
        else if (f < 4915200) { src = wv; dst = g_hWv; off = f - 4325376; }
        else if (f < 5505024) { src = wo; dst = g_hWo; off = f - 4915200; }
        else if (f < 7864320) { src = w1; dst = g_hW1; off = f - 5505024; }
        else                  { src = w2; dst = g_hW2; off = f - 7864320; }
        float4 v = *(const float4*)(src + off);
        half2* d = (half2*)(dst + off);
        d[0] = __floats2half2_rn(v.x, v.y);
        d[1] = __floats2half2_rn(v.z, v.w);
        if (f < 3145728) {   // states chunk: also prefill y1 for Wo split-K
            float4 b = *(const float4*)(bo + (off % D_DIM));
            float4 o;
            o.x = v.x * ALPHA_C + b.x; o.y = v.y * ALPHA_C + b.y;
            o.z = v.z * ALPHA_C + b.z; o.w = v.w * ALPHA_C + b.w;
            *(float4*)(y1 + off) = o;
        }
    }
}

// ---------------------------------------------------------------------------
// fp16 tensor-core GEMM, BK=32, 4-stage cp.async pipeline (1 barrier / 32-k).
// C = A(N x K) @ W(M x K)^T  (+ fused epilogue)
// Split-K via gridDim.z (E_ATOMIC: partials RED.ADD into prefilled C).
// E_QKV fuses the gating computation from raw Q outputs.
// ---------------------------------------------------------------------------
enum { E_QKV = 0, E_ATOMIC = 1, E_GELU = 2 };

#define SROW32 40        // halves per smem row (32 data + 8 pad)
#define MM_STAGES 4
#define STG32  (128 * SROW32)                       // halves per operand/stage
#define MM_SMEM (2 * MM_STAGES * STG32 * 2 + 512)   // bytes (+ wsum)

template <int EPI>
__global__ __launch_bounds__(256, 2) void mm_h(
    const __half* __restrict__ A,
    const __half* __restrict__ W0, const __half* __restrict__ W1h, const __half* __restrict__ W2h,
    const float* __restrict__ bp0, const float* __restrict__ bp1, const float* __restrict__ bp2,
    void* __restrict__ C0, void* __restrict__ C1, void* __restrict__ C2,
    const float* __restrict__ gw, const float* __restrict__ gbb,
    const float* __restrict__ gai, float* __restrict__ gate_out,
    int K, int ldc)
{
    extern __shared__ __half smh[];
    __half* Asm = smh;
    __half* Bsm = smh + MM_STAGES * STG32;
    float*  wsum = (float*)(smh + 2 * MM_STAGES * STG32);

    int sel = 0, mblk = blockIdx.x;
    const __half* W = W0; const float* bias = bp0; void* C = C0;
    if (EPI == E_QKV) {
        sel  = blockIdx.x / 6;
        mblk = blockIdx.x % 6;
        if (sel == 1) { W = W1h; bias = bp1; C = C1; }
        else if (sel == 2) { W = W2h; bias = bp2; C = C2; }
    }

    const int n0 = blockIdx.y * 128;
    const int m0 = mblk * 128;
    const int tid  = threadIdx.x;
    const int lane = tid & 31;
    const int wid  = tid >> 5;
    const int wr = (wid >> 1) * 32;
    const int wc = (wid & 1)  * 64;
    const int g = lane >> 2;
    const int c = lane & 3;

    const int KK   = K / gridDim.z;           // K per split
    const int koff = blockIdx.z * KK;
    const int NK   = KK >> 5;

    if (EPI == E_QKV && sel == 0 && tid < 128) {
        const int hd = tid & 63, base = (tid >> 6) * 256;
        wsum[tid] = gw[base + hd] + gw[base + 64 + hd]
                  + gw[base + 128 + hd] + gw[base + 192 + hd];
    }

    float acc[2][8][4];
#pragma unroll
    for (int mf = 0; mf < 2; mf++)
#pragma unroll
        for (int nf = 0; nf < 8; nf++)
#pragma unroll
            for (int r = 0; r < 4; r++) acc[mf][nf][r] = 0.f;

    const __half* Ab = A + (size_t)n0 * K + koff;
    const __half* Wb = W + (size_t)m0 * K + koff;

    const int lr0 = (tid + 0)   >> 2, ls0 = ((tid + 0)   & 3) * 8;
    const int lr1 = (tid + 256) >> 2, ls1 = ((tid + 256) & 3) * 8;

    // prologue: stages 0..2
#pragma unroll
    for (int s = 0; s < 3; s++) {
        cp16(&Asm[s * STG32 + lr0 * SROW32 + ls0], Ab + (size_t)lr0 * K + s * 32 + ls0);
        cp16(&Asm[s * STG32 + lr1 * SROW32 + ls1], Ab + (size_t)lr1 * K + s * 32 + ls1);
        cp16(&Bsm[s * STG32 + lr0 * SROW32 + ls0], Wb + (size_t)lr0 * K + s * 32 + ls0);
        cp16(&Bsm[s * STG32 + lr1 * SROW32 + ls1], Wb + (size_t)lr1 * K + s * 32 + ls1);
        CP_COMMIT();
    }

    const int a_row = wr + (lane & 15);
    const int a_kb  = (lane >> 4) * 8;
    const int b_row = wc + (lane & 7) + ((lane >> 4) & 1) * 8;
    const int b_kb  = ((lane >> 3) & 1) * 8;

    for (int i = 0; i < NK; i++) {
        const int s   = i % MM_STAGES;
        const int rem = NK - i - 1;
        if      (rem >= 2) CP_WAIT(2);
        else if (rem == 1) CP_WAIT(1);
        else               CP_WAIT(0);
        __syncthreads();

        if (i + 3 < NK) {
            const int s2 = (i + 3) % MM_STAGES;
            const int kt = (i + 3) * 32;
            cp16(&Asm[s2 * STG32 + lr0 * SROW32 + ls0], Ab + (size_t)lr0 * K + kt + ls0);
            cp16(&Asm[s2 * STG32 + lr1 * SROW32 + ls1], Ab + (size_t)lr1 * K + kt + ls1);
            cp16(&Bsm[s2 * STG32 + lr0 * SROW32 + ls0], Wb + (size_t)lr0 * K + kt + ls0);
            cp16(&Bsm[s2 * STG32 + lr1 * SROW32 + ls1], Wb + (size_t)lr1 * K + kt + ls1);
            CP_COMMIT();
        }

#pragma unroll
        for (int kh = 0; kh < 2; kh++) {
            unsigned af[2][4], bf[4][4];
            unsigned abase = sm_u32(&Asm[s * STG32 + a_row * SROW32 + kh * 16 + a_kb]);
            ldsm_x4(af[0], abase);
            ldsm_x4(af[1], abase + 16 * SROW32 * 2);
            unsigned bbase = sm_u32(&Bsm[s * STG32 + b_row * SROW32 + kh * 16 + b_kb]);
#pragma unroll
            for (int bi = 0; bi < 4; bi++)
                ldsm_x4(bf[bi], bbase + bi * 16 * SROW32 * 2);

#pragma unroll
            for (int mf = 0; mf < 2; mf++)
#pragma unroll
                for (int nf = 0; nf < 8; nf++) {
                    const int bi = nf >> 1, hi = (nf & 1) * 2;
                    mma_fp16(acc[mf][nf], af[mf], bf[bi][hi], bf[bi][hi + 1]);
                }
        }
    }

    // gate-path per-thread weights
    float was[16], wbs[16], bsum_a = 0.f, bsum_b = 0.f, gah = 0.f;
    if (EPI == E_QKV && sel == 0) {
#pragma unroll
        for (int nf = 0; nf < 8; nf++) {
            const int hd = (wc + nf * 8 + c * 2) & 63;
            was[nf * 2]     = wsum[hd];
            was[nf * 2 + 1] = wsum[hd + 1];
            wbs[nf * 2]     = wsum[64 + hd];
            wbs[nf * 2 + 1] = wsum[64 + hd + 1];
        }
        bsum_a = gbb[0] + gbb[1] + gbb[2] + gbb[3];
        bsum_b = gbb[4] + gbb[5] + gbb[6] + gbb[7];
        gah = gai[(m0 + wc) >> 6];
    }

    // Epilogue
#pragma unroll
    for (int mf = 0; mf < 2; mf++) {
#pragma unroll
        for (int r2 = 0; r2 < 2; r2++) {
            const int n = n0 + wr + mf * 16 + g + r2 * 8;
            float sa = 0.f, sb = 0.f;
#pragma unroll
            for (int nf = 0; nf < 8; nf++) {
                const int m = m0 + wc + nf * 8 + c * 2;
                if (EPI == E_ATOMIC) {
                    atomicAdd(&((float*)C)[(size_t)n * ldc + m],     acc[mf][nf][r2 * 2]);
                    atomicAdd(&((float*)C)[(size_t)n * ldc + m + 1], acc[mf][nf][r2 * 2 + 1]);
                } else {
                    float v0 = acc[mf][nf][r2 * 2]     + bias[m];
                    float v1 = acc[mf][nf][r2 * 2 + 1] + bias[m + 1];
                    if (EPI == E_QKV) {
                        if (sel == 0) {
                            sa += v0 * was[nf * 2] + v1 * was[nf * 2 + 1];
                            sb += v0 * wbs[nf * 2] + v1 * wbs[nf * 2 + 1];
                            v0 *= QSCALE; v1 *= QSCALE;
                        }
                        const int t = n >> 2, b = n & 3, h = m >> 6, hd = m & 63;
                        *(half2*)&((__half*)C)[(((size_t)(b * H_DIM + h) * T_DIM) + t) * HD_DIM + hd] =
                            __floats2half2_rn(v0, v1);
                    } else { // E_GELU (exact) -> fp16
                        float g0 = 0.5f * v0 * (1.f + erff(v0 * 0.70710678118654752f));
                        float g1 = 0.5f * v1 * (1.f + erff(v1 * 0.70710678118654752f));
                        *(half2*)&((__half*)C)[(size_t)n * ldc + m] = __floats2half2_rn(g0, g1);
                    }
                }
            }
            if (EPI == E_QKV && sel == 0) {
                sa += __shfl_xor_sync(0xffffffffu, sa, 1);
                sa += __shfl_xor_sync(0xffffffffu, sa, 2);
                sb += __shfl_xor_sync(0xffffffffu, sb, 1);
                sb += __shfl_xor_sync(0xffffffffu, sb, 2);
                if (c == 0) {
                    float ga = 1.f / (1.f + __expf(-(sa + bsum_a)));
                    float gb = 1.f / (1.f + __expf(-(sb + bsum_b)));
                    const int t = n >> 2, b = n & 3, h = (m0 + wc) >> 6;
                    gate_out[(b * H_DIM + h) * T_DIM + t] = ga * (gb * gah - 1.f) + 2.f;
                }
            }
        }
    }
}

// ---------------------------------------------------------------------------
// Tensor-core flash attention + fused pb passthrough copy.  (R13-verified)
// Grid (8, 48): 128 q-rows/CTA, 8 warps x 16 rows.
// 3-stage KV ring -> ONE block barrier per tile; pb staged per-warp.
// smem: Q 128x72h | K 3x64x72h | V 3x64x72h | PB 128x72f | gates 128f
// ---------------------------------------------------------------------------
#define FA_QH   (128 * 72)     // halves
#define FA_KVH  (64 * 72)      // halves per stage
#define FA_SMEM (FA_QH * 2 + 6 * FA_KVH * 2 + 128 * 72 * 4 + 512)

__global__ __launch_bounds__(256, 2) void flash_attn_h(
    const __half* __restrict__ q, const __half* __restrict__ k,
    const __half* __restrict__ v, const float* __restrict__ pb,
    const float* __restrict__ gate, __half* __restrict__ ctx,
    float* __restrict__ outpb)
{
    extern __shared__ __half smh[];
    __half* Qs  = smh;                        // 128x72 h
    __half* Ks  = smh + FA_QH;                // 3 stages 64x72 h
    __half* Vs  = smh + FA_QH + 3 * FA_KVH;   // 3 stages
    float*  PBs = (float*)(smh + FA_QH + 6 * FA_KVH);   // 128x72 f
    float*  Gs  = PBs + 128 * 72;

    const int bh   = blockIdx.y;
    const int q0   = blockIdx.x * 128;
    const int tid  = threadIdx.x;
    const int lane = tid & 31;
    const int w    = tid >> 5;
    const int g    = lane >> 2;
    const int c    = lane & 3;

    const __half* qg = q + ((size_t)bh * T_DIM + q0) * 64;
    const __half* kg = k + (size_t)bh * 65536;
    const __half* vg = v + (size_t)bh * 65536;
    const float*  pbg = pb + ((size_t)bh * T_DIM + q0) * T_DIM;

    // group 1: Q + KV tile0 (stage 0) + pb tile0 ; group 2: KV tile1 (stage 1)
#pragma unroll
    for (int i = tid; i < 1024; i += 256) {
        int row = i >> 3, ch = (i & 7) * 8;
        cp16(&Qs[row * 72 + ch], qg + row * 64 + ch);
    }
#pragma unroll
    for (int i = tid; i < 512; i += 256) {
        int row = i >> 3, ch = (i & 7) * 8;
        cp16(&Ks[row * 72 + ch], kg + row * 64 + ch);
        cp16(&Vs[row * 72 + ch], vg + row * 64 + ch);
    }
#pragma unroll
    for (int it = 0; it < 8; it++) {
        int cidx = lane + it * 32;
        int row  = w * 16 + (cidx >> 4);
        int chf  = (cidx & 15) * 4;
        cp16(&PBs[row * 72 + chf], pbg + (size_t)row * T_DIM + chf);
    }
    CP_COMMIT();
#pragma unroll
    for (int i = tid; i < 512; i += 256) {
        int row = i >> 3, ch = (i & 7) * 8;
        cp16(&Ks[FA_KVH + row * 72 + ch], kg + 4096 + row * 64 + ch);
        cp16(&Vs[FA_KVH + row * 72 + ch], vg + 4096 + row * 64 + ch);
    }
    CP_COMMIT();
    if (tid < 128) Gs[tid] = gate[bh * T_DIM + q0 + tid];

    CP_WAIT(1);
    __syncthreads();

    // Q fragments (persist in registers)
    unsigned af[4][4];
    {
        const int ar  = w * 16 + (lane & 15);
        const int akb = (lane >> 4) * 8;
#pragma unroll
        for (int ks = 0; ks < 4; ks++)
            ldsm_x4(af[ks], sm_u32(&Qs[ar * 72 + ks * 16 + akb]));
    }

    float m0 = -1e30f, m1 = -1e30f, l0 = 0.f, l1 = 0.f;
    float oacc[8][4];
#pragma unroll
    for (int hb = 0; hb < 8; hb++)
#pragma unroll
        for (int j = 0; j < 4; j++) oacc[hb][j] = 0.f;

    const float gr0 = Gs[w * 16 + g];
    const float gr1 = Gs[w * 16 + g + 8];
    float* opb0 = outpb + ((size_t)bh * T_DIM + q0 + w * 16 + g) * T_DIM;
    float* opb1 = opb0 + 8 * T_DIM;

    const int brow = (lane & 7) + ((lane >> 4) & 1) * 8;
    const int bkb  = ((lane >> 3) & 1) * 8;
    const int vr   = lane & 15;
    const int vcb  = (lane >> 4) * 8;
    const int prow0 = (w * 16 + g) * 72;

    for (int t = 0; t < 16; t++) {
        const int st = t % 3;
        // (1) KV(t) ready. outstanding allowed: {PB(t), KV(t+1)}  [t=15: {PB15}]
        if (t) {
            if (t < 15) CP_WAIT(2); else CP_WAIT(1);
            __syncthreads();
        }
        // (1b) early prefetch KV(t+2) into stage (t+2)%3 (freed by barrier above)
        if (t + 2 < 16) {
            const __half* ks2 = kg + (t + 2) * 4096;
            const __half* vs2 = vg + (t + 2) * 4096;
            __half* kd = Ks + ((t + 2) % 3) * FA_KVH;
            __half* vd = Vs + ((t + 2) % 3) * FA_KVH;
#pragma unroll
            for (int i = tid; i < 512; i += 256) {
                int row = i >> 3, ch = (i & 7) * 8;
                cp16(&kd[row * 72 + ch], ks2 + row * 64 + ch);
                cp16(&vd[row * 72 + ch], vs2 + row * 64 + ch);
            }
            CP_COMMIT();
        }
        const __half* Kb = Ks + st * FA_KVH;
        const __half* Vb = Vs + st * FA_KVH;

        // (2) S = Q @ K^T
        float sacc[8][4];
#pragma unroll
        for (int nb = 0; nb < 8; nb++)
#pragma unroll
            for (int j = 0; j < 4; j++) sacc[nb][j] = 0.f;

#pragma unroll
        for (int nb2 = 0; nb2 < 4; nb2++) {
#pragma unroll
            for (int ks = 0; ks < 4; ks++) {
                unsigned bf[4];
                ldsm_x4(bf, sm_u32(&Kb[(nb2 * 16 + brow) * 72 + ks * 16 + bkb]));
                mma_fp16(sacc[nb2 * 2],     af[ks], bf[0], bf[1]);
                mma_fp16(sacc[nb2 * 2 + 1], af[ks], bf[2], bf[3]);
            }
        }

        // (3) PB(t) ready (warp-local rows).
        if (t < 14) CP_WAIT(1); else CP_WAIT(0);
        __syncwarp();

        // (4) logits + passthrough + online softmax
        float mx0 = -1e30f, mx1 = -1e30f;
#pragma unroll
        for (int nb = 0; nb < 8; nb++) {
            float2 p0 = *(const float2*)&PBs[prow0 + nb * 8 + c * 2];
            float2 p1 = *(const float2*)&PBs[prow0 + 8 * 72 + nb * 8 + c * 2];
            *(float2*)&opb0[t * 64 + nb * 8 + c * 2] = p0;
            *(float2*)&opb1[t * 64 + nb * 8 + c * 2] = p1;
            sacc[nb][0] = 32.f * sacc[nb][0] + gr0 * p0.x;
            sacc[nb][1] = 32.f * sacc[nb][1] + gr0 * p0.y;
            sacc[nb][2] = 32.f * sacc[nb][2] + gr1 * p1.x;
            sacc[nb][3] = 32.f * sacc[nb][3] + gr1 * p1.y;
            mx0 = fmaxf(mx0, fmaxf(sacc[nb][0], sacc[nb][1]));
            mx1 = fmaxf(mx1, fmaxf(sacc[nb][2], sacc[nb][3]));
        }
        mx0 = fmaxf(mx0, __shfl_xor_sync(0xffffffffu, mx0, 1));
        mx0 = fmaxf(mx0, __shfl_xor_sync(0xffffffffu, mx0, 2));
        mx1 = fmaxf(mx1, __shfl_xor_sync(0xffffffffu, mx1, 1));
        mx1 = fmaxf(mx1, __shfl_xor_sync(0xffffffffu, mx1, 2));

        const float nm0 = fmaxf(m0, mx0), nm1 = fmaxf(m1, mx1);
        const float corr0 = __expf(m0 - nm0), corr1 = __expf(m1 - nm1);
        m0 = nm0; m1 = nm1;

        unsigned pa[4][4];
        float s0 = 0.f, s1 = 0.f;
#pragma unroll
        for (int nb = 0; nb < 8; nb++) {
            float e0 = __expf(sacc[nb][0] - nm0);
            float e1 = __expf(sacc[nb][1] - nm0);
            float e2 = __expf(sacc[nb][2] - nm1);
            float e3 = __expf(sacc[nb][3] - nm1);
            s0 += e0 + e1; s1 += e2 + e3;
            const int kp = nb >> 1, off = (nb & 1) * 2;
            half2 h0 = __floats2half2_rn(e0, e1);
            half2 h1 = __floats2half2_rn(e2, e3);
            pa[kp][off]     = *(unsigned*)&h0;
            pa[kp][off + 1] = *(unsigned*)&h1;
        }
        s0 += __shfl_xor_sync(0xffffffffu, s0, 1);
        s0 += __shfl_xor_sync(0xffffffffu, s0, 2);
        s1 += __shfl_xor_sync(0xffffffffu, s1, 1);
        s1 += __shfl_xor_sync(0xffffffffu, s1, 2);
        l0 = l0 * corr0 + s0;
        l1 = l1 * corr1 + s1;

#pragma unroll
        for (int hb = 0; hb < 8; hb++) {
            oacc[hb][0] *= corr0; oacc[hb][1] *= corr0;
            oacc[hb][2] *= corr1; oacc[hb][3] *= corr1;
        }

        // (5) warp done reading its PB rows -> warp-local prefetch of pb(t+1)
        __syncwarp();
        if (t + 1 < 16) {
#pragma unroll
            for (int it = 0; it < 8; it++) {
                int cidx = lane + it * 32;
                int row  = w * 16 + (cidx >> 4);
                int chf  = (cidx & 15) * 4;
                cp16(&PBs[row * 72 + chf],
                     pbg + (size_t)row * T_DIM + (t + 1) * 64 + chf);
            }
            CP_COMMIT();
        }

        // (6) out += P @ V   (V loaded transposed); no bottom barrier needed
#pragma unroll
        for (int kp = 0; kp < 4; kp++) {
#pragma unroll
            for (int hb2 = 0; hb2 < 4; hb2++) {
                unsigned bv[4];
                ldsm_x4_t(bv, sm_u32(&Vb[(kp * 16 + vr) * 72 + hb2 * 16 + vcb]));
                mma_fp16(oacc[hb2 * 2],     pa[kp], bv[0], bv[1]);
                mma_fp16(oacc[hb2 * 2 + 1], pa[kp], bv[2], bv[3]);
            }
        }
    }

    // write ctx (fp16, (T,B,D) layout) for Wo GEMM
    const float i0 = 1.f / l0, i1 = 1.f / l1;
    const int b = bh / H_DIM, hh = bh % H_DIM;
    const int t0g = q0 + w * 16 + g;
#pragma unroll
    for (int hb = 0; hb < 8; hb++) {
        const int col = hh * 64 + hb * 8 + c * 2;
        half2 o0 = __floats2half2_rn(oacc[hb][0] * i0, oacc[hb][1] * i0);
        half2 o1 = __floats2half2_rn(oacc[hb][2] * i1, oacc[hb][3] * i1);
        *(half2*)&ctx[(size_t)(t0g * B_DIM + b) * D_DIM + col]       = o0;
        *(half2*)&ctx[(size_t)((t0g + 8) * B_DIM + b) * D_DIM + col] = o1;
    }
}

// ---------------------------------------------------------------------------
// LayerNorm (optionally emits fp16 copy and/or y2pre = r*ALPHA + b2)
// ---------------------------------------------------------------------------
__global__ void layernorm_kernel(const float* __restrict__ in,
                                 const float* __restrict__ g,
                                 const float* __restrict__ b,
                                 float* __restrict__ out,
                                 __half* __restrict__ hout,
                                 const float* __restrict__ rb2,
                                 float* __restrict__ y2o)
{
    const int row = blockIdx.x, tid = threadIdx.x;
    const float* xr = in + (size_t)row * D_DIM;
    float v0 = xr[tid], v1 = xr[tid + 256], v2 = xr[tid + 512];
    float s  = v0 + v1 + v2;
    float sq = v0 * v0 + v1 * v1 + v2 * v2;
#pragma unroll
    for (int o = 16; o; o >>= 1) {
        s  += __shfl_xor_sync(0xffffffffu, s,  o);
        sq += __shfl_xor_sync(0xffffffffu, sq, o);
    }
    __shared__ float ss[8], sqs[8], stats[2];
    const int w = tid >> 5, lane = tid & 31;
    if (lane == 0) { ss[w] = s; sqs[w] = sq; }
    __syncthreads();
    if (tid == 0) {
        float S = 0.f, SQ = 0.f;
        for (int i = 0; i < 8; i++) { S += ss[i]; SQ += sqs[i]; }
        float mu  = S * (1.f / 768.f);
        float var = SQ * (1.f / 768.f) - mu * mu;
        stats[0] = mu;
        stats[1] = rsqrtf(var + 1e-5f);
    }
    __syncthreads();
    const float mu = stats[0], rstd = stats[1];
    float r0 = (v0 - mu) * rstd * g[tid]       + b[tid];
    float r1 = (v1 - mu) * rstd * g[tid + 256] + b[tid + 256];
    float r2 = (v2 - mu) * rstd * g[tid + 512] + b[tid + 512];
    float* orow = out + (size_t)row * D_DIM;
    orow[tid] = r0; orow[tid + 256] = r1; orow[tid + 512] = r2;
    if (hout) {
        __half* hrow = hout + (size_t)row * D_DIM;
        hrow[tid] = __float2half_rn(r0);
        hrow[tid + 256] = __float2half_rn(r1);
        hrow[tid + 512] = __float2half_rn(r2);
    }
    if (y2o) {   // prefill for FFN2 split-K: y2 = x*ALPHA + b2
        float* yr = y2o + (size_t)row * D_DIM;
        yr[tid]       = r0 * ALPHA_C + rb2[tid];
        yr[tid + 256] = r1 * ALPHA_C + rb2[tid + 256];
        yr[tid + 512] = r2 * ALPHA_C + rb2[tid + 512];
    }
}

// ---------------------------------------------------------------------------
// Launch
// ---------------------------------------------------------------------------
extern "C" void kernel_launch(void* const* d_in, const int* in_sizes, int n_in,
                              void* d_out, int out_size)
{
    const float* states = (const float*)d_in[0];
    const float* pb     = (const float*)d_in[1];
    const float* Wq = (const float*)d_in[2];   const float* bq = (const float*)d_in[3];
    const float* Wk = (const float*)d_in[4];   const float* bk = (const float*)d_in[5];
    const float* Wv = (const float*)d_in[6];   const float* bv = (const float*)d_in[7];
    const float* Wo = (const float*)d_in[8];   const float* bo = (const float*)d_in[9];
    const float* grep_w = (const float*)d_in[10];
    const float* grep_b = (const float*)d_in[11];
    const float* grep_a = (const float*)d_in[12];
    const float* ln1_g  = (const float*)d_in[13];
    const float* ln1_b  = (const float*)d_in[14];
    const float* W1 = (const float*)d_in[15];  const float* b1 = (const float*)d_in[16];
    const float* W2 = (const float*)d_in[17];  const float* b2 = (const float*)d_in[18];
    const float* ln2_g  = (const float*)d_in[19];
    const float* ln2_b  = (const float*)d_in[20];
    float* out = (float*)d_out;

    __half *hstates, *hWq, *hWk, *hWv, *hWo, *hW1, *hW2;
    __half *hq, *hk, *hv, *hctx, *hx, *hh;
    float  *gate, *y1, *x, *y2;
    cudaGetSymbolAddress((void**)&hstates, g_hstates);
    cudaGetSymbolAddress((void**)&hWq, g_hWq);
    cudaGetSymbolAddress((void**)&hWk, g_hWk);
    cudaGetSymbolAddress((void**)&hWv, g_hWv);
    cudaGetSymbolAddress((void**)&hWo, g_hWo);
    cudaGetSymbolAddress((void**)&hW1, g_hW1);
    cudaGetSymbolAddress((void**)&hW2, g_hW2);
    cudaGetSymbolAddress((void**)&hq,  g_hq);
    cudaGetSymbolAddress((void**)&hk,  g_hk);
    cudaGetSymbolAddress((void**)&hv,  g_hv);
    cudaGetSymbolAddress((void**)&hctx, g_hctx);
    cudaGetSymbolAddress((void**)&hx,  g_hx);
    cudaGetSymbolAddress((void**)&hh,  g_hh);
    cudaGetSymbolAddress((void**)&gate, g_gate);
    cudaGetSymbolAddress((void**)&y1,  g_y1);
    cudaGetSymbolAddress((void**)&x,   g_x);
    cudaGetSymbolAddress((void**)&y2,  g_y2);

    cudaFuncSetAttribute(mm_h<E_QKV>,    cudaFuncAttributeMaxDynamicSharedMemorySize, MM_SMEM);
    cudaFuncSetAttribute(mm_h<E_ATOMIC>, cudaFuncAttributeMaxDynamicSharedMemorySize, MM_SMEM);
    cudaFuncSetAttribute(mm_h<E_GELU>,   cudaFuncAttributeMaxDynamicSharedMemorySize, MM_SMEM);
    cudaFuncSetAttribute(flash_attn_h,   cudaFuncAttributeMaxDynamicSharedMemorySize, FA_SMEM);

    const dim3 blk(256);

    // fp32 -> fp16 for states + weights ; also prefills y1 = states*ALPHA + bo
    f2h_all<<<2496, blk>>>(states, Wq, Wk, Wv, Wo, W1, W2, bo, y1);

    // Fused QKV projections + gate computation (fp16 tensor cores)
    mm_h<E_QKV><<<dim3(18, 32, 1), blk, MM_SMEM>>>(
        hstates, hWq, hWk, hWv, bq, bk, bv, hq, hk, hv,
        grep_w, grep_b, grep_a, gate, D_DIM, 0);

    // tensor-core flash attention (+ fused pb passthrough into out)
    flash_attn_h<<<dim3(T_DIM / 128, NHEADS), blk, FA_SMEM>>>(
        hq, hk, hv, pb, gate, hctx, out + (size_t)NROWS * D_DIM);

    // Wo projection: split-K2 atomic GEMM into prefilled y1, then LN1 (+y2 prefill)
    mm_h<E_ATOMIC><<<dim3(6, 32, 2), blk, MM_SMEM>>>(
        hctx, hWo, nullptr, nullptr, nullptr, nullptr, nullptr,
        y1, nullptr, nullptr,
        nullptr, nullptr, nullptr, nullptr, D_DIM, D_DIM);
    layernorm_kernel<<<NROWS, blk>>>(y1, ln1_g, ln1_b, x, hx, b2, y2);

    // FFN
    mm_h<E_GELU><<<dim3(24, 32, 1), blk, MM_SMEM>>>(
        hx, hW1, nullptr, nullptr, b1, nullptr, nullptr,
        hh, nullptr, nullptr,
        nullptr, nullptr, nullptr, nullptr, D_DIM, FF_DIM);
    mm_h<E_ATOMIC><<<dim3(6, 32, 2), blk, MM_SMEM>>>(
        hh, hW2, nullptr, nullptr, nullptr, nullptr, nullptr,
        y2, nullptr, nullptr,
        nullptr, nullptr, nullptr, nullptr, FF_DIM, D_DIM);
    layernorm_kernel<<<NROWS, blk>>>(y2, ln2_g, ln2_b, out, nullptr, nullptr, nullptr);
}

// round 16
// speedup vs baseline: 1.0308x; 1.0101x over previous
#include <cuda_runtime.h>
#include <cuda_fp16.h>
#include <math.h>

// ---------------------------------------------------------------------------
// Problem constants
// ---------------------------------------------------------------------------
#define T_DIM   1024
#define B_DIM   4
#define D_DIM   768
#define H_DIM   12
#define HD_DIM  64
#define FF_DIM  3072
#define NROWS   4096          // T*B
#define NHEADS  48            // B*H
#define ALPHA_C 2.2133638394006434f   // 24^0.25
#define QSCALE  0.00390625f           // 0.125/32

// ---------------------------------------------------------------------------
// Scratch (device globals: allocation-free rule)
// ---------------------------------------------------------------------------
__device__ __half g_hstates[NROWS * D_DIM];
__device__ __half g_hWq[D_DIM * D_DIM];
__device__ __half g_hWk[D_DIM * D_DIM];
__device__ __half g_hWv[D_DIM * D_DIM];
__device__ __half g_hWo[D_DIM * D_DIM];
__device__ __half g_hW1[FF_DIM * D_DIM];
__device__ __half g_hW2[D_DIM * FF_DIM];
__device__ __half g_hq [NHEADS * T_DIM * HD_DIM];
__device__ __half g_hk [NHEADS * T_DIM * HD_DIM];
__device__ __half g_hv [NHEADS * T_DIM * HD_DIM];
__device__ __half g_hctx[NROWS * D_DIM];
__device__ __half g_hx [NROWS * D_DIM];
__device__ __half g_hh [NROWS * FF_DIM];
__device__ float  g_gate[NHEADS * T_DIM];
__device__ float  g_y1 [NROWS * D_DIM];
__device__ float  g_x  [NROWS * D_DIM];
__device__ float  g_y2 [NROWS * D_DIM];

// ---------------------------------------------------------------------------
// PTX helpers
// ---------------------------------------------------------------------------
__device__ __forceinline__ unsigned sm_u32(const void* p) {
    return (unsigned)__cvta_generic_to_shared(p);
}
__device__ __forceinline__ void cp16(void* s, const void* g) {
    asm volatile("cp.async.ca.shared.global [%0], [%1], 16;\n"
                 :: "r"(sm_u32(s)), "l"(g));
}
#define CP_COMMIT() asm volatile("cp.async.commit_group;\n")
#define CP_WAIT(N)  asm volatile("cp.async.wait_group %0;\n" :: "n"(N))

__device__ __forceinline__ void ldsm_x4(unsigned* f, unsigned addr) {
    asm volatile("ldmatrix.sync.aligned.m8n8.x4.shared.b16 {%0,%1,%2,%3}, [%4];"
                 : "=r"(f[0]), "=r"(f[1]), "=r"(f[2]), "=r"(f[3]) : "r"(addr));
}
__device__ __forceinline__ void ldsm_x4_t(unsigned* f, unsigned addr) {
    asm volatile("ldmatrix.sync.aligned.m8n8.x4.trans.shared.b16 {%0,%1,%2,%3}, [%4];"
                 : "=r"(f[0]), "=r"(f[1]), "=r"(f[2]), "=r"(f[3]) : "r"(addr));
}
__device__ __forceinline__ void mma_fp16(float* d, const unsigned* a,
                                         unsigned b0, unsigned b1) {
    asm volatile(
        "mma.sync.aligned.m16n8k16.row.col.f32.f16.f16.f32 "
        "{%0,%1,%2,%3}, {%4,%5,%6,%7}, {%8,%9}, {%0,%1,%2,%3};\n"
        : "+f"(d[0]), "+f"(d[1]), "+f"(d[2]), "+f"(d[3])
        : "r"(a[0]), "r"(a[1]), "r"(a[2]), "r"(a[3]), "r"(b0), "r"(b1));
}

// ---------------------------------------------------------------------------
// fp32 -> fp16 conversion of states + weights; ALSO emits y1 = states*ALPHA+bo
// ---------------------------------------------------------------------------
__global__ void f2h_all(const float* __restrict__ s0, const float* __restrict__ wq,
                        const float* __restrict__ wk, const float* __restrict__ wv,
                        const float* __restrict__ wo, const float* __restrict__ w1,
                        const float* __restrict__ w2,
                        const float* __restrict__ bo, float* __restrict__ y1)
{
    const int total4 = 2555904;  // 10,223,616 floats / 4
    for (int i = blockIdx.x * blockDim.x + threadIdx.x; i < total4;
         i += gridDim.x * blockDim.x) {
        int f = i * 4;
        const float* src; __half* dst; int off;
        if      (f < 3145728) { src = s0; dst = g_hstates; off = f; }
        else if (f < 3735552) { src = wq; dst = g_hWq; off = f - 3145728; }
        else if (f < 4325376) { src = wk; dst = g_hWk; off = f - 3735552; }
        else if (f < 4915200) { src = wv; dst = g_hWv; off = f - 4325376; }
        else if (f < 5505024) { src = wo; dst = g_hWo; off = f - 4915200; }
        else if (f < 7864320) { src = w1; dst = g_hW1; off = f - 5505024; }
        else                  { src = w2; dst = g_hW2; off = f - 7864320; }
        float4 v = *(const float4*)(src + off);
        half2* d = (half2*)(dst + off);
        d[0] = __floats2half2_rn(v.x, v.y);
        d[1] = __floats2half2_rn(v.z, v.w);
        if (f < 3145728) {   // states chunk: also prefill y1 for Wo split-K
            float4 b = *(const float4*)(bo + (off % D_DIM));
            float4 o;
            o.x = v.x * ALPHA_C + b.x; o.y = v.y * ALPHA_C + b.y;
            o.z = v.z * ALPHA_C + b.z; o.w = v.w * ALPHA_C + b.w;
            *(float4*)(y1 + off) = o;
        }
    }
}

// ---------------------------------------------------------------------------
// fp16 tensor-core GEMM, BK=64, 3-stage cp.async pipeline (1 barrier / 64-k).
// C = A(N x K) @ W(M x K)^T  (+ fused epilogue)
// Split-K via gridDim.z (E_ATOMIC: partials RED.ADD into prefilled C).
// E_QKV fuses the gating computation from raw Q outputs.
// ---------------------------------------------------------------------------
enum { E_QKV = 0, E_ATOMIC = 1, E_GELU = 2 };

#define SROW64 72        // halves per smem row (64 data + 8 pad)
#define MM_STAGES 3
#define STG64  (128 * SROW64)                       // halves per operand/stage
#define MM_SMEM (2 * MM_STAGES * STG64 * 2 + 512)   // bytes (+ wsum)

template <int EPI>
__global__ __launch_bounds__(256, 2) void mm_h(
    const __half* __restrict__ A,
    const __half* __restrict__ W0, const __half* __restrict__ W1h, const __half* __restrict__ W2h,
    const float* __restrict__ bp0, const float* __restrict__ bp1, const float* __restrict__ bp2,
    void* __restrict__ C0, void* __restrict__ C1, void* __restrict__ C2,
    const float* __restrict__ gw, const float* __restrict__ gbb,
    const float* __restrict__ gai, float* __restrict__ gate_out,
    int K, int ldc)
{
    extern __shared__ __half smh[];
    __half* Asm = smh;
    __half* Bsm = smh + MM_STAGES * STG64;
    float*  wsum = (float*)(smh + 2 * MM_STAGES * STG64);

    int sel = 0, mblk = blockIdx.x;
    const __half* W = W0; const float* bias = bp0; void* C = C0;
    if (EPI == E_QKV) {
        sel  = blockIdx.x / 6;
        mblk = blockIdx.x % 6;
        if (sel == 1) { W = W1h; bias = bp1; C = C1; }
        else if (sel == 2) { W = W2h; bias = bp2; C = C2; }
    }

    const int n0 = blockIdx.y * 128;
    const int m0 = mblk * 128;
    const int tid  = threadIdx.x;
    const int lane = tid & 31;
    const int wid  = tid >> 5;
    const int wr = (wid >> 1) * 32;
    const int wc = (wid & 1)  * 64;
    const int g = lane >> 2;
    const int c = lane & 3;

    const int KK   = K / gridDim.z;           // K per split
    const int koff = blockIdx.z * KK;
    const int NK   = KK >> 6;                 // 64-k iterations

    if (EPI == E_QKV && sel == 0 && tid < 128) {
        const int hd = tid & 63, base = (tid >> 6) * 256;
        wsum[tid] = gw[base + hd] + gw[base + 64 + hd]
                  + gw[base + 128 + hd] + gw[base + 192 + hd];
    }

    float acc[2][8][4];
#pragma unroll
    for (int mf = 0; mf < 2; mf++)
#pragma unroll
        for (int nf = 0; nf < 8; nf++)
#pragma unroll
            for (int r = 0; r < 4; r++) acc[mf][nf][r] = 0.f;

    const __half* Ab = A + (size_t)n0 * K + koff;
    const __half* Wb = W + (size_t)m0 * K + koff;

    // loader: 1024 16B-chunks per operand per stage; 4 per thread per operand
    // chunk cidx = tid + u*256 -> row = cidx>>3 (0..127), seg = (cidx&7)*8
    const int lrowu[4] = { (tid) >> 3, (tid + 256) >> 3, (tid + 512) >> 3, (tid + 768) >> 3 };
    const int lsegu[4] = { (tid & 7) * 8, ((tid + 256) & 7) * 8,
                           ((tid + 512) & 7) * 8, ((tid + 768) & 7) * 8 };

    // prologue: stages 0..1
#pragma unroll
    for (int s = 0; s < 2; s++) {
#pragma unroll
        for (int u = 0; u < 4; u++) {
            cp16(&Asm[s * STG64 + lrowu[u] * SROW64 + lsegu[u]],
                 Ab + (size_t)lrowu[u] * K + s * 64 + lsegu[u]);
            cp16(&Bsm[s * STG64 + lrowu[u] * SROW64 + lsegu[u]],
                 Wb + (size_t)lrowu[u] * K + s * 64 + lsegu[u]);
        }
        CP_COMMIT();
    }

    const int a_row = wr + (lane & 15);
    const int a_kb  = (lane >> 4) * 8;
    const int b_row = wc + (lane & 7) + ((lane >> 4) & 1) * 8;
    const int b_kb  = ((lane >> 3) & 1) * 8;

    for (int i = 0; i < NK; i++) {
        const int s = i % MM_STAGES;
        if (i + 1 < NK) CP_WAIT(1); else CP_WAIT(0);
        __syncthreads();

        if (i + 2 < NK) {
            const int s2 = (i + 2) % MM_STAGES;
            const int kt = (i + 2) * 64;
#pragma unroll
            for (int u = 0; u < 4; u++) {
                cp16(&Asm[s2 * STG64 + lrowu[u] * SROW64 + lsegu[u]],
                     Ab + (size_t)lrowu[u] * K + kt + lsegu[u]);
                cp16(&Bsm[s2 * STG64 + lrowu[u] * SROW64 + lsegu[u]],
                     Wb + (size_t)lrowu[u] * K + kt + lsegu[u]);
            }
            CP_COMMIT();
        }

#pragma unroll
        for (int kh = 0; kh < 4; kh++) {
            unsigned af[2][4], bf[4][4];
            unsigned abase = sm_u32(&Asm[s * STG64 + a_row * SROW64 + kh * 16 + a_kb]);
            ldsm_x4(af[0], abase);
            ldsm_x4(af[1], abase + 16 * SROW64 * 2);
            unsigned bbase = sm_u32(&Bsm[s * STG64 + b_row * SROW64 + kh * 16 + b_kb]);
#pragma unroll
            for (int bi = 0; bi < 4; bi++)
                ldsm_x4(bf[bi], bbase + bi * 16 * SROW64 * 2);

#pragma unroll
            for (int mf = 0; mf < 2; mf++)
#pragma unroll
                for (int nf = 0; nf < 8; nf++) {
                    const int bi = nf >> 1, hi = (nf & 1) * 2;
                    mma_fp16(acc[mf][nf], af[mf], bf[bi][hi], bf[bi][hi + 1]);
                }
        }
    }

    // gate-path per-thread weights
    float was[16], wbs[16], bsum_a = 0.f, bsum_b = 0.f, gah = 0.f;
    if (EPI == E_QKV && sel == 0) {
#pragma unroll
        for (int nf = 0; nf < 8; nf++) {
            const int hd = (wc + nf * 8 + c * 2) & 63;
            was[nf * 2]     = wsum[hd];
            was[nf * 2 + 1] = wsum[hd + 1];
            wbs[nf * 2]     = wsum[64 + hd];
            wbs[nf * 2 + 1] = wsum[64 + hd + 1];
        }
        bsum_a = gbb[0] + gbb[1] + gbb[2] + gbb[3];
        bsum_b = gbb[4] + gbb[5] + gbb[6] + gbb[7];
        gah = gai[(m0 + wc) >> 6];
    }

    // Epilogue
#pragma unroll
    for (int mf = 0; mf < 2; mf++) {
#pragma unroll
        for (int r2 = 0; r2 < 2; r2++) {
            const int n = n0 + wr + mf * 16 + g + r2 * 8;
            float sa = 0.f, sb = 0.f;
#pragma unroll
            for (int nf = 0; nf < 8; nf++) {
                const int m = m0 + wc + nf * 8 + c * 2;
                if (EPI == E_ATOMIC) {
                    atomicAdd(&((float*)C)[(size_t)n * ldc + m],     acc[mf][nf][r2 * 2]);
                    atomicAdd(&((float*)C)[(size_t)n * ldc + m + 1], acc[mf][nf][r2 * 2 + 1]);
                } else {
                    float v0 = acc[mf][nf][r2 * 2]     + bias[m];
                    float v1 = acc[mf][nf][r2 * 2 + 1] + bias[m + 1];
                    if (EPI == E_QKV) {
                        if (sel == 0) {
                            sa += v0 * was[nf * 2] + v1 * was[nf * 2 + 1];
                            sb += v0 * wbs[nf * 2] + v1 * wbs[nf * 2 + 1];
                            v0 *= QSCALE; v1 *= QSCALE;
                        }
                        const int t = n >> 2, b = n & 3, h = m >> 6, hd = m & 63;
                        *(half2*)&((__half*)C)[(((size_t)(b * H_DIM + h) * T_DIM) + t) * HD_DIM + hd] =
                            __floats2half2_rn(v0, v1);
                    } else { // E_GELU (exact) -> fp16
                        float g0 = 0.5f * v0 * (1.f + erff(v0 * 0.70710678118654752f));
                        float g1 = 0.5f * v1 * (1.f + erff(v1 * 0.70710678118654752f));
                        *(half2*)&((__half*)C)[(size_t)n * ldc + m] = __floats2half2_rn(g0, g1);
                    }
                }
            }
            if (EPI == E_QKV && sel == 0) {
                sa += __shfl_xor_sync(0xffffffffu, sa, 1);
                sa += __shfl_xor_sync(0xffffffffu, sa, 2);
                sb += __shfl_xor_sync(0xffffffffu, sb, 1);
                sb += __shfl_xor_sync(0xffffffffu, sb, 2);
                if (c == 0) {
                    float ga = 1.f / (1.f + __expf(-(sa + bsum_a)));
                    float gb = 1.f / (1.f + __expf(-(sb + bsum_b)));
                    const int t = n >> 2, b = n & 3, h = (m0 + wc) >> 6;
                    gate_out[(b * H_DIM + h) * T_DIM + t] = ga * (gb * gah - 1.f) + 2.f;
                }
            }
        }
    }
}

// ---------------------------------------------------------------------------
// Tensor-core flash attention + fused pb passthrough copy.  (R13-verified)
// Grid (8, 48): 128 q-rows/CTA, 8 warps x 16 rows.
// 3-stage KV ring -> ONE block barrier per tile; pb staged per-warp.
// smem: Q 128x72h | K 3x64x72h | V 3x64x72h | PB 128x72f | gates 128f
// ---------------------------------------------------------------------------
#define FA_QH   (128 * 72)     // halves
#define FA_KVH  (64 * 72)      // halves per stage
#define FA_SMEM (FA_QH * 2 + 6 * FA_KVH * 2 + 128 * 72 * 4 + 512)

__global__ __launch_bounds__(256, 2) void flash_attn_h(
    const __half* __restrict__ q, const __half* __restrict__ k,
    const __half* __restrict__ v, const float* __restrict__ pb,
    const float* __restrict__ gate, __half* __restrict__ ctx,
    float* __restrict__ outpb)
{
    extern __shared__ __half smh[];
    __half* Qs  = smh;                        // 128x72 h
    __half* Ks  = smh + FA_QH;                // 3 stages 64x72 h
    __half* Vs  = smh + FA_QH + 3 * FA_KVH;   // 3 stages
    float*  PBs = (float*)(smh + FA_QH + 6 * FA_KVH);   // 128x72 f
    float*  Gs  = PBs + 128 * 72;

    const int bh   = blockIdx.y;
    const int q0   = blockIdx.x * 128;
    const int tid  = threadIdx.x;
    const int lane = tid & 31;
    const int w    = tid >> 5;
    const int g    = lane >> 2;
    const int c    = lane & 3;

    const __half* qg = q + ((size_t)bh * T_DIM + q0) * 64;
    const __half* kg = k + (size_t)bh * 65536;
    const __half* vg = v + (size_t)bh * 65536;
    const float*  pbg = pb + ((size_t)bh * T_DIM + q0) * T_DIM;

    // group 1: Q + KV tile0 (stage 0) + pb tile0 ; group 2: KV tile1 (stage 1)
#pragma unroll
    for (int i = tid; i < 1024; i += 256) {
        int row = i >> 3, ch = (i & 7) * 8;
        cp16(&Qs[row * 72 + ch], qg + row * 64 + ch);
    }
#pragma unroll
    for (int i = tid; i < 512; i += 256) {
        int row = i >> 3, ch = (i & 7) * 8;
        cp16(&Ks[row * 72 + ch], kg + row * 64 + ch);
        cp16(&Vs[row * 72 + ch], vg + row * 64 + ch);
    }
#pragma unroll
    for (int it = 0; it < 8; it++) {
        int cidx = lane + it * 32;
        int row  = w * 16 + (cidx >> 4);
        int chf  = (cidx & 15) * 4;
        cp16(&PBs[row * 72 + chf], pbg + (size_t)row * T_DIM + chf);
    }
    CP_COMMIT();
#pragma unroll
    for (int i = tid; i < 512; i += 256) {
        int row = i >> 3, ch = (i & 7) * 8;
        cp16(&Ks[FA_KVH + row * 72 + ch], kg + 4096 + row * 64 + ch);
        cp16(&Vs[FA_KVH + row * 72 + ch], vg + 4096 + row * 64 + ch);
    }
    CP_COMMIT();
    if (tid < 128) Gs[tid] = gate[bh * T_DIM + q0 + tid];

    CP_WAIT(1);
    __syncthreads();

    // Q fragments (persist in registers)
    unsigned af[4][4];
    {
        const int ar  = w * 16 + (lane & 15);
        const int akb = (lane >> 4) * 8;
#pragma unroll
        for (int ks = 0; ks < 4; ks++)
            ldsm_x4(af[ks], sm_u32(&Qs[ar * 72 + ks * 16 + akb]));
    }

    float m0 = -1e30f, m1 = -1e30f, l0 = 0.f, l1 = 0.f;
    float oacc[8][4];
#pragma unroll
    for (int hb = 0; hb < 8; hb++)
#pragma unroll
        for (int j = 0; j < 4; j++) oacc[hb][j] = 0.f;

    const float gr0 = Gs[w * 16 + g];
    const float gr1 = Gs[w * 16 + g + 8];
    float* opb0 = outpb + ((size_t)bh * T_DIM + q0 + w * 16 + g) * T_DIM;
    float* opb1 = opb0 + 8 * T_DIM;

    const int brow = (lane & 7) + ((lane >> 4) & 1) * 8;
    const int bkb  = ((lane >> 3) & 1) * 8;
    const int vr   = lane & 15;
    const int vcb  = (lane >> 4) * 8;
    const int prow0 = (w * 16 + g) * 72;

    for (int t = 0; t < 16; t++) {
        const int st = t % 3;
        // (1) KV(t) ready. outstanding allowed: {PB(t), KV(t+1)}  [t=15: {PB15}]
        if (t) {
            if (t < 15) CP_WAIT(2); else CP_WAIT(1);
            __syncthreads();
        }
        // (1b) early prefetch KV(t+2) into stage (t+2)%3 (freed by barrier above)
        if (t + 2 < 16) {
            const __half* ks2 = kg + (t + 2) * 4096;
            const __half* vs2 = vg + (t + 2) * 4096;
            __half* kd = Ks + ((t + 2) % 3) * FA_KVH;
            __half* vd = Vs + ((t + 2) % 3) * FA_KVH;
#pragma unroll
            for (int i = tid; i < 512; i += 256) {
                int row = i >> 3, ch = (i & 7) * 8;
                cp16(&kd[row * 72 + ch], ks2 + row * 64 + ch);
                cp16(&vd[row * 72 + ch], vs2 + row * 64 + ch);
            }
            CP_COMMIT();
        }
        const __half* Kb = Ks + st * FA_KVH;
        const __half* Vb = Vs + st * FA_KVH;

        // (2) S = Q @ K^T
        float sacc[8][4];
#pragma unroll
        for (int nb = 0; nb < 8; nb++)
#pragma unroll
            for (int j = 0; j < 4; j++) sacc[nb][j] = 0.f;

#pragma unroll
        for (int nb2 = 0; nb2 < 4; nb2++) {
#pragma unroll
            for (int ks = 0; ks < 4; ks++) {
                unsigned bf[4];
                ldsm_x4(bf, sm_u32(&Kb[(nb2 * 16 + brow) * 72 + ks * 16 + bkb]));
                mma_fp16(sacc[nb2 * 2],     af[ks], bf[0], bf[1]);
                mma_fp16(sacc[nb2 * 2 + 1], af[ks], bf[2], bf[3]);
            }
        }

        // (3) PB(t) ready (warp-local rows).
        if (t < 14) CP_WAIT(1); else CP_WAIT(0);
        __syncwarp();

        // (4) logits + passthrough + online softmax
        float mx0 = -1e30f, mx1 = -1e30f;
#pragma unroll
        for (int nb = 0; nb < 8; nb++) {
            float2 p0 = *(const float2*)&PBs[prow0 + nb * 8 + c * 2];
            float2 p1 = *(const float2*)&PBs[prow0 + 8 * 72 + nb * 8 + c * 2];
            *(float2*)&opb0[t * 64 + nb * 8 + c * 2] = p0;
            *(float2*)&opb1[t * 64 + nb * 8 + c * 2] = p1;
            sacc[nb][0] = 32.f * sacc[nb][0] + gr0 * p0.x;
            sacc[nb][1] = 32.f * sacc[nb][1] + gr0 * p0.y;
            sacc[nb][2] = 32.f * sacc[nb][2] + gr1 * p1.x;
            sacc[nb][3] = 32.f * sacc[nb][3] + gr1 * p1.y;
            mx0 = fmaxf(mx0, fmaxf(sacc[nb][0], sacc[nb][1]));
            mx1 = fmaxf(mx1, fmaxf(sacc[nb][2], sacc[nb][3]));
        }
        mx0 = fmaxf(mx0, __shfl_xor_sync(0xffffffffu, mx0, 1));
        mx0 = fmaxf(mx0, __shfl_xor_sync(0xffffffffu, mx0, 2));
        mx1 = fmaxf(mx1, __shfl_xor_sync(0xffffffffu, mx1, 1));
        mx1 = fmaxf(mx1, __shfl_xor_sync(0xffffffffu, mx1, 2));

        const float nm0 = fmaxf(m0, mx0), nm1 = fmaxf(m1, mx1);
        const float corr0 = __expf(m0 - nm0), corr1 = __expf(m1 - nm1);
        m0 = nm0; m1 = nm1;

        unsigned pa[4][4];
        float s0 = 0.f, s1 = 0.f;
#pragma unroll
        for (int nb = 0; nb < 8; nb++) {
            float e0 = __expf(sacc[nb][0] - nm0);
            float e1 = __expf(sacc[nb][1] - nm0);
            float e2 = __expf(sacc[nb][2] - nm1);
            float e3 = __expf(sacc[nb][3] - nm1);
            s0 += e0 + e1; s1 += e2 + e3;
            const int kp = nb >> 1, off = (nb & 1) * 2;
            half2 h0 = __floats2half2_rn(e0, e1);
            half2 h1 = __floats2half2_rn(e2, e3);
            pa[kp][off]     = *(unsigned*)&h0;
            pa[kp][off + 1] = *(unsigned*)&h1;
        }
        s0 += __shfl_xor_sync(0xffffffffu, s0, 1);
        s0 += __shfl_xor_sync(0xffffffffu, s0, 2);
        s1 += __shfl_xor_sync(0xffffffffu, s1, 1);
        s1 += __shfl_xor_sync(0xffffffffu, s1, 2);
        l0 = l0 * corr0 + s0;
        l1 = l1 * corr1 + s1;

#pragma unroll
        for (int hb = 0; hb < 8; hb++) {
            oacc[hb][0] *= corr0; oacc[hb][1] *= corr0;
            oacc[hb][2] *= corr1; oacc[hb][3] *= corr1;
        }

        // (5) warp done reading its PB rows -> warp-local prefetch of pb(t+1)
        __syncwarp();
        if (t + 1 < 16) {
#pragma unroll
            for (int it = 0; it < 8; it++) {
                int cidx = lane + it * 32;
                int row  = w * 16 + (cidx >> 4);
                int chf  = (cidx & 15) * 4;
                cp16(&PBs[row * 72 + chf],
                     pbg + (size_t)row * T_DIM + (t + 1) * 64 + chf);
            }
            CP_COMMIT();
        }

        // (6) out += P @ V   (V loaded transposed); no bottom barrier needed
#pragma unroll
        for (int kp = 0; kp < 4; kp++) {
#pragma unroll
            for (int hb2 = 0; hb2 < 4; hb2++) {
                unsigned bv[4];
                ldsm_x4_t(bv, sm_u32(&Vb[(kp * 16 + vr) * 72 + hb2 * 16 + vcb]));
                mma_fp16(oacc[hb2 * 2],     pa[kp], bv[0], bv[1]);
                mma_fp16(oacc[hb2 * 2 + 1], pa[kp], bv[2], bv[3]);
            }
        }
    }

    // write ctx (fp16, (T,B,D) layout) for Wo GEMM
    const float i0 = 1.f / l0, i1 = 1.f / l1;
    const int b = bh / H_DIM, hh = bh % H_DIM;
    const int t0g = q0 + w * 16 + g;
#pragma unroll
    for (int hb = 0; hb < 8; hb++) {
        const int col = hh * 64 + hb * 8 + c * 2;
        half2 o0 = __floats2half2_rn(oacc[hb][0] * i0, oacc[hb][1] * i0);
        half2 o1 = __floats2half2_rn(oacc[hb][2] * i1, oacc[hb][3] * i1);
        *(half2*)&ctx[(size_t)(t0g * B_DIM + b) * D_DIM + col]       = o0;
        *(half2*)&ctx[(size_t)((t0g + 8) * B_DIM + b) * D_DIM + col] = o1;
    }
}

// ---------------------------------------------------------------------------
// LayerNorm (optionally emits fp16 copy and/or y2pre = r*ALPHA + b2)
// ---------------------------------------------------------------------------
__global__ void layernorm_kernel(const float* __restrict__ in,
                                 const float* __restrict__ g,
                                 const float* __restrict__ b,
                                 float* __restrict__ out,
                                 __half* __restrict__ hout,
                                 const float* __restrict__ rb2,
                                 float* __restrict__ y2o)
{
    const int row = blockIdx.x, tid = threadIdx.x;
    const float* xr = in + (size_t)row * D_DIM;
    float v0 = xr[tid], v1 = xr[tid + 256], v2 = xr[tid + 512];
    float s  = v0 + v1 + v2;
    float sq = v0 * v0 + v1 * v1 + v2 * v2;
#pragma unroll
    for (int o = 16; o; o >>= 1) {
        s  += __shfl_xor_sync(0xffffffffu, s,  o);
        sq += __shfl_xor_sync(0xffffffffu, sq, o);
    }
    __shared__ float ss[8], sqs[8], stats[2];
    const int w = tid >> 5, lane = tid & 31;
    if (lane == 0) { ss[w] = s; sqs[w] = sq; }
    __syncthreads();
    if (tid == 0) {
        float S = 0.f, SQ = 0.f;
        for (int i = 0; i < 8; i++) { S += ss[i]; SQ += sqs[i]; }
        float mu  = S * (1.f / 768.f);
        float var = SQ * (1.f / 768.f) - mu * mu;
        stats[0] = mu;
        stats[1] = rsqrtf(var + 1e-5f);
    }
    __syncthreads();
    const float mu = stats[0], rstd = stats[1];
    float r0 = (v0 - mu) * rstd * g[tid]       + b[tid];
    float r1 = (v1 - mu) * rstd * g[tid + 256] + b[tid + 256];
    float r2 = (v2 - mu) * rstd * g[tid + 512] + b[tid + 512];
    float* orow = out + (size_t)row * D_DIM;
    orow[tid] = r0; orow[tid + 256] = r1; orow[tid + 512] = r2;
    if (hout) {
        __half* hrow = hout + (size_t)row * D_DIM;
        hrow[tid] = __float2half_rn(r0);
        hrow[tid + 256] = __float2half_rn(r1);
        hrow[tid + 512] = __float2half_rn(r2);
    }
    if (y2o) {   // prefill for FFN2 split-K: y2 = x*ALPHA + b2
        float* yr = y2o + (size_t)row * D_DIM;
        yr[tid]       = r0 * ALPHA_C + rb2[tid];
        yr[tid + 256] = r1 * ALPHA_C + rb2[tid + 256];
        yr[tid + 512] = r2 * ALPHA_C + rb2[tid + 512];
    }
}

// ---------------------------------------------------------------------------
// Launch
// ---------------------------------------------------------------------------
extern "C" void kernel_launch(void* const* d_in, const int* in_sizes, int n_in,
                              void* d_out, int out_size)
{
    const float* states = (const float*)d_in[0];
    const float* pb     = (const float*)d_in[1];
    const float* Wq = (const float*)d_in[2];   const float* bq = (const float*)d_in[3];
    const float* Wk = (const float*)d_in[4];   const float* bk = (const float*)d_in[5];
    const float* Wv = (const float*)d_in[6];   const float* bv = (const float*)d_in[7];
    const float* Wo = (const float*)d_in[8];   const float* bo = (const float*)d_in[9];
    const float* grep_w = (const float*)d_in[10];
    const float* grep_b = (const float*)d_in[11];
    const float* grep_a = (const float*)d_in[12];
    const float* ln1_g  = (const float*)d_in[13];
    const float* ln1_b  = (const float*)d_in[14];
    const float* W1 = (const float*)d_in[15];  const float* b1 = (const float*)d_in[16];
    const float* W2 = (const float*)d_in[17];  const float* b2 = (const float*)d_in[18];
    const float* ln2_g  = (const float*)d_in[19];
    const float* ln2_b  = (const float*)d_in[20];
    float* out = (float*)d_out;

    __half *hstates, *hWq, *hWk, *hWv, *hWo, *hW1, *hW2;
    __half *hq, *hk, *hv, *hctx, *hx, *hh;
    float  *gate, *y1, *x, *y2;
    cudaGetSymbolAddress((void**)&hstates, g_hstates);
    cudaGetSymbolAddress((void**)&hWq, g_hWq);
    cudaGetSymbolAddress((void**)&hWk, g_hWk);
    cudaGetSymbolAddress((void**)&hWv, g_hWv);
    cudaGetSymbolAddress((void**)&hWo, g_hWo);
    cudaGetSymbolAddress((void**)&hW1, g_hW1);
    cudaGetSymbolAddress((void**)&hW2, g_hW2);
    cudaGetSymbolAddress((void**)&hq,  g_hq);
    cudaGetSymbolAddress((void**)&hk,  g_hk);
    cudaGetSymbolAddress((void**)&hv,  g_hv);
    cudaGetSymbolAddress((void**)&hctx, g_hctx);
    cudaGetSymbolAddress((void**)&hx,  g_hx);
    cudaGetSymbolAddress((void**)&hh,  g_hh);
    cudaGetSymbolAddress((void**)&gate, g_gate);
    cudaGetSymbolAddress((void**)&y1,  g_y1);
    cudaGetSymbolAddress((void**)&x,   g_x);
    cudaGetSymbolAddress((void**)&y2,  g_y2);

    cudaFuncSetAttribute(mm_h<E_QKV>,    cudaFuncAttributeMaxDynamicSharedMemorySize, MM_SMEM);
    cudaFuncSetAttribute(mm_h<E_ATOMIC>, cudaFuncAttributeMaxDynamicSharedMemorySize, MM_SMEM);
    cudaFuncSetAttribute(mm_h<E_GELU>,   cudaFuncAttributeMaxDynamicSharedMemorySize, MM_SMEM);
    cudaFuncSetAttribute(flash_attn_h,   cudaFuncAttributeMaxDynamicSharedMemorySize, FA_SMEM);

    const dim3 blk(256);

    // fp32 -> fp16 for states + weights ; also prefills y1 = states*ALPHA + bo
    f2h_all<<<2496, blk>>>(states, Wq, Wk, Wv, Wo, W1, W2, bo, y1);

    // Fused QKV projections + gate computation (fp16 tensor cores)
    mm_h<E_QKV><<<dim3(18, 32, 1), blk, MM_SMEM>>>(
        hstates, hWq, hWk, hWv, bq, bk, bv, hq, hk, hv,
        grep_w, grep_b, grep_a, gate, D_DIM, 0);

    // tensor-core flash attention (+ fused pb passthrough into out)
    flash_attn_h<<<dim3(T_DIM / 128, NHEADS), blk, FA_SMEM>>>(
        hq, hk, hv, pb, gate, hctx, out + (size_t)NROWS * D_DIM);

    // Wo projection: split-K2 atomic GEMM into prefilled y1, then LN1 (+y2 prefill)
    mm_h<E_ATOMIC><<<dim3(6, 32, 2), blk, MM_SMEM>>>(
        hctx, hWo, nullptr, nullptr, nullptr, nullptr, nullptr,
        y1, nullptr, nullptr,
        nullptr, nullptr, nullptr, nullptr, D_DIM, D_DIM);
    layernorm_kernel<<<NROWS, blk>>>(y1, ln1_g, ln1_b, x, hx, b2, y2);

    // FFN
    mm_h<E_GELU><<<dim3(24, 32, 1), blk, MM_SMEM>>>(
        hx, hW1, nullptr, nullptr, b1, nullptr, nullptr,
        hh, nullptr, nullptr,
        nullptr, nullptr, nullptr, nullptr, D_DIM, FF_DIM);
    mm_h<E_ATOMIC><<<dim3(6, 32, 2), blk, MM_SMEM>>>(
        hh, hW2, nullptr, nullptr, nullptr, nullptr, nullptr,
        y2, nullptr, nullptr,
        nullptr, nullptr, nullptr, nullptr, FF_DIM, D_DIM);
    layernorm_kernel<<<NROWS, blk>>>(y2, ln2_g, ln2_b, out, nullptr, nullptr, nullptr);
}

// round 17
// speedup vs baseline: 1.0857x; 1.0533x over previous
#include <cuda_runtime.h>
#include <cuda_fp16.h>
#include <math.h>

// ---------------------------------------------------------------------------
// Problem constants
// ---------------------------------------------------------------------------
#define T_DIM   1024
#define B_DIM   4
#define D_DIM   768
#define H_DIM   12
#define HD_DIM  64
#define FF_DIM  3072
#define NROWS   4096          // T*B
#define NHEADS  48            // B*H
#define ALPHA_C 2.2133638394006434f   // 24^0.25
#define QSCALE  0.00390625f           // 0.125/32

// ---------------------------------------------------------------------------
// Scratch (device globals: allocation-free rule)
// ---------------------------------------------------------------------------
__device__ __half g_hstates[NROWS * D_DIM];
__device__ __half g_hWq[D_DIM * D_DIM];
__device__ __half g_hWk[D_DIM * D_DIM];
__device__ __half g_hWv[D_DIM * D_DIM];
__device__ __half g_hWo[D_DIM * D_DIM];
__device__ __half g_hW1[FF_DIM * D_DIM];
__device__ __half g_hW2[D_DIM * FF_DIM];
__device__ __half g_hq [NHEADS * T_DIM * HD_DIM];
__device__ __half g_hk [NHEADS * T_DIM * HD_DIM];
__device__ __half g_hv [NHEADS * T_DIM * HD_DIM];
__device__ __half g_hctx[NROWS * D_DIM];
__device__ __half g_hx [NROWS * D_DIM];
__device__ __half g_hh [NROWS * FF_DIM];
__device__ float  g_gate[NHEADS * T_DIM];
__device__ float  g_y1 [NROWS * D_DIM];
__device__ float  g_x  [NROWS * D_DIM];
__device__ float  g_y2 [NROWS * D_DIM];

// ---------------------------------------------------------------------------
// PTX helpers
// ---------------------------------------------------------------------------
__device__ __forceinline__ unsigned sm_u32(const void* p) {
    return (unsigned)__cvta_generic_to_shared(p);
}
__device__ __forceinline__ void cp16(void* s, const void* g) {
    asm volatile("cp.async.ca.shared.global [%0], [%1], 16;\n"
                 :: "r"(sm_u32(s)), "l"(g));
}
#define CP_COMMIT() asm volatile("cp.async.commit_group;\n")
#define CP_WAIT(N)  asm volatile("cp.async.wait_group %0;\n" :: "n"(N))

__device__ __forceinline__ void ldsm_x4(unsigned* f, unsigned addr) {
    asm volatile("ldmatrix.sync.aligned.m8n8.x4.shared.b16 {%0,%1,%2,%3}, [%4];"
                 : "=r"(f[0]), "=r"(f[1]), "=r"(f[2]), "=r"(f[3]) : "r"(addr));
}
__device__ __forceinline__ void ldsm_x4_t(unsigned* f, unsigned addr) {
    asm volatile("ldmatrix.sync.aligned.m8n8.x4.trans.shared.b16 {%0,%1,%2,%3}, [%4];"
                 : "=r"(f[0]), "=r"(f[1]), "=r"(f[2]), "=r"(f[3]) : "r"(addr));
}
__device__ __forceinline__ void mma_fp16(float* d, const unsigned* a,
                                         unsigned b0, unsigned b1) {
    asm volatile(
        "mma.sync.aligned.m16n8k16.row.col.f32.f16.f16.f32 "
        "{%0,%1,%2,%3}, {%4,%5,%6,%7}, {%8,%9}, {%0,%1,%2,%3};\n"
        : "+f"(d[0]), "+f"(d[1]), "+f"(d[2]), "+f"(d[3])
        : "r"(a[0]), "r"(a[1]), "r"(a[2]), "r"(a[3]), "r"(b0), "r"(b1));
}

// ---------------------------------------------------------------------------
// fp32 -> fp16 conversion of states + weights; ALSO emits y1 = states*ALPHA+bo
// ---------------------------------------------------------------------------
__global__ void f2h_all(const float* __restrict__ s0, const float* __restrict__ wq,
                        const float* __restrict__ wk, const float* __restrict__ wv,
                        const float* __restrict__ wo, const float* __restrict__ w1,
                        const float* __restrict__ w2,
                        const float* __restrict__ bo, float* __restrict__ y1)
{
    const int total4 = 2555904;  // 10,223,616 floats / 4
    for (int i = blockIdx.x * blockDim.x + threadIdx.x; i < total4;
         i += gridDim.x * blockDim.x) {
        int f = i * 4;
        const float* src; __half* dst; int off;
        if      (f < 3145728) { src = s0; dst = g_hstates; off = f; }
        else if (f < 3735552) { src = wq; dst = g_hWq; off = f - 3145728; }
        else if (f < 4325376) { src = wk; dst = g_hWk; off = f - 3735552; }
        else if (f < 4915200) { src = wv; dst = g_hWv; off = f - 4325376; }
        else if (f < 5505024) { src = wo; dst = g_hWo; off = f - 4915200; }
        else if (f < 7864320) { src = w1; dst = g_hW1; off = f - 5505024; }
        else                  { src = w2; dst = g_hW2; off = f - 7864320; }
        float4 v = *(const float4*)(src + off);
        half2* d = (half2*)(dst + off);
        d[0] = __floats2half2_rn(v.x, v.y);
        d[1] = __floats2half2_rn(v.z, v.w);
        if (f < 3145728) {   // states chunk: also prefill y1 for Wo split-K
            float4 b = *(const float4*)(bo + (off % D_DIM));
            float4 o;
            o.x = v.x * ALPHA_C + b.x; o.y = v.y * ALPHA_C + b.y;
            o.z = v.z * ALPHA_C + b.z; o.w = v.w * ALPHA_C + b.w;
            *(float4*)(y1 + off) = o;
        }
    }
}

// ---------------------------------------------------------------------------
// fp16 tensor-core GEMM, BK=64, 3-stage cp.async pipeline (1 barrier / 64-k).
// C = A(N x K) @ W(M x K)^T  (+ fused epilogue)
// Split-K via gridDim.z (E_ATOMIC: partials RED.ADD into prefilled C).
// E_QKV fuses the gating computation from raw Q outputs.
// ---------------------------------------------------------------------------
enum { E_QKV = 0, E_ATOMIC = 1, E_GELU = 2 };

#define SROW64 72        // halves per smem row (64 data + 8 pad)
#define MM_STAGES 3
#define STG64  (128 * SROW64)                       // halves per operand/stage
#define MM_SMEM (2 * MM_STAGES * STG64 * 2 + 512)   // bytes (+ wsum)

template <int EPI>
__global__ __launch_bounds__(256, 2) void mm_h(
    const __half* __restrict__ A,
    const __half* __restrict__ W0, const __half* __restrict__ W1h, const __half* __restrict__ W2h,
    const float* __restrict__ bp0, const float* __restrict__ bp1, const float* __restrict__ bp2,
    void* __restrict__ C0, void* __restrict__ C1, void* __restrict__ C2,
    const float* __restrict__ gw, const float* __restrict__ gbb,
    const float* __restrict__ gai, float* __restrict__ gate_out,
    int K, int ldc)
{
    extern __shared__ __half smh[];
    __half* Asm = smh;
    __half* Bsm = smh + MM_STAGES * STG64;
    float*  wsum = (float*)(smh + 2 * MM_STAGES * STG64);

    int sel = 0, mblk = blockIdx.x;
    const __half* W = W0; const float* bias = bp0; void* C = C0;
    if (EPI == E_QKV) {
        sel  = blockIdx.x / 6;
        mblk = blockIdx.x % 6;
        if (sel == 1) { W = W1h; bias = bp1; C = C1; }
        else if (sel == 2) { W = W2h; bias = bp2; C = C2; }
    }

    const int n0 = blockIdx.y * 128;
    const int m0 = mblk * 128;
    const int tid  = threadIdx.x;
    const int lane = tid & 31;
    const int wid  = tid >> 5;
    const int wr = (wid >> 1) * 32;
    const int wc = (wid & 1)  * 64;
    const int g = lane >> 2;
    const int c = lane & 3;

    const int KK   = K / gridDim.z;           // K per split
    const int koff = blockIdx.z * KK;
    const int NK   = KK >> 6;                 // 64-k iterations

    if (EPI == E_QKV && sel == 0 && tid < 128) {
        const int hd = tid & 63, base = (tid >> 6) * 256;
        wsum[tid] = gw[base + hd] + gw[base + 64 + hd]
                  + gw[base + 128 + hd] + gw[base + 192 + hd];
    }

    float acc[2][8][4];
#pragma unroll
    for (int mf = 0; mf < 2; mf++)
#pragma unroll
        for (int nf = 0; nf < 8; nf++)
#pragma unroll
            for (int r = 0; r < 4; r++) acc[mf][nf][r] = 0.f;

    const __half* Ab = A + (size_t)n0 * K + koff;
    const __half* Wb = W + (size_t)m0 * K + koff;

    // loader: 1024 16B-chunks per operand per stage; 4 per thread per operand
    const int lrowu[4] = { (tid) >> 3, (tid + 256) >> 3, (tid + 512) >> 3, (tid + 768) >> 3 };
    const int lsegu[4] = { (tid & 7) * 8, ((tid + 256) & 7) * 8,
                           ((tid + 512) & 7) * 8, ((tid + 768) & 7) * 8 };

    // prologue: stages 0..1
#pragma unroll
    for (int s = 0; s < 2; s++) {
#pragma unroll
        for (int u = 0; u < 4; u++) {
            cp16(&Asm[s * STG64 + lrowu[u] * SROW64 + lsegu[u]],
                 Ab + (size_t)lrowu[u] * K + s * 64 + lsegu[u]);
            cp16(&Bsm[s * STG64 + lrowu[u] * SROW64 + lsegu[u]],
                 Wb + (size_t)lrowu[u] * K + s * 64 + lsegu[u]);
        }
        CP_COMMIT();
    }

    const int a_row = wr + (lane & 15);
    const int a_kb  = (lane >> 4) * 8;
    const int b_row = wc + (lane & 7) + ((lane >> 4) & 1) * 8;
    const int b_kb  = ((lane >> 3) & 1) * 8;

    for (int i = 0; i < NK; i++) {
        const int s = i % MM_STAGES;
        if (i + 1 < NK) CP_WAIT(1); else CP_WAIT(0);
        __syncthreads();

        if (i + 2 < NK) {
            const int s2 = (i + 2) % MM_STAGES;
            const int kt = (i + 2) * 64;
#pragma unroll
            for (int u = 0; u < 4; u++) {
                cp16(&Asm[s2 * STG64 + lrowu[u] * SROW64 + lsegu[u]],
                     Ab + (size_t)lrowu[u] * K + kt + lsegu[u]);
                cp16(&Bsm[s2 * STG64 + lrowu[u] * SROW64 + lsegu[u]],
                     Wb + (size_t)lrowu[u] * K + kt + lsegu[u]);
            }
            CP_COMMIT();
        }

#pragma unroll
        for (int kh = 0; kh < 4; kh++) {
            unsigned af[2][4], bf[4][4];
            unsigned abase = sm_u32(&Asm[s * STG64 + a_row * SROW64 + kh * 16 + a_kb]);
            ldsm_x4(af[0], abase);
            ldsm_x4(af[1], abase + 16 * SROW64 * 2);
            unsigned bbase = sm_u32(&Bsm[s * STG64 + b_row * SROW64 + kh * 16 + b_kb]);
#pragma unroll
            for (int bi = 0; bi < 4; bi++)
                ldsm_x4(bf[bi], bbase + bi * 16 * SROW64 * 2);

#pragma unroll
            for (int mf = 0; mf < 2; mf++)
#pragma unroll
                for (int nf = 0; nf < 8; nf++) {
                    const int bi = nf >> 1, hi = (nf & 1) * 2;
                    mma_fp16(acc[mf][nf], af[mf], bf[bi][hi], bf[bi][hi + 1]);
                }
        }
    }

    // gate-path per-thread weights
    float was[16], wbs[16], bsum_a = 0.f, bsum_b = 0.f, gah = 0.f;
    if (EPI == E_QKV && sel == 0) {
#pragma unroll
        for (int nf = 0; nf < 8; nf++) {
            const int hd = (wc + nf * 8 + c * 2) & 63;
            was[nf * 2]     = wsum[hd];
            was[nf * 2 + 1] = wsum[hd + 1];
            wbs[nf * 2]     = wsum[64 + hd];
            wbs[nf * 2 + 1] = wsum[64 + hd + 1];
        }
        bsum_a = gbb[0] + gbb[1] + gbb[2] + gbb[3];
        bsum_b = gbb[4] + gbb[5] + gbb[6] + gbb[7];
        gah = gai[(m0 + wc) >> 6];
    }

    // Epilogue
#pragma unroll
    for (int mf = 0; mf < 2; mf++) {
#pragma unroll
        for (int r2 = 0; r2 < 2; r2++) {
            const int n = n0 + wr + mf * 16 + g + r2 * 8;
            float sa = 0.f, sb = 0.f;
#pragma unroll
            for (int nf = 0; nf < 8; nf++) {
                const int m = m0 + wc + nf * 8 + c * 2;
                if (EPI == E_ATOMIC) {
                    atomicAdd(&((float*)C)[(size_t)n * ldc + m],     acc[mf][nf][r2 * 2]);
                    atomicAdd(&((float*)C)[(size_t)n * ldc + m + 1], acc[mf][nf][r2 * 2 + 1]);
                } else {
                    float v0 = acc[mf][nf][r2 * 2]     + bias[m];
                    float v1 = acc[mf][nf][r2 * 2 + 1] + bias[m + 1];
                    if (EPI == E_QKV) {
                        if (sel == 0) {
                            sa += v0 * was[nf * 2] + v1 * was[nf * 2 + 1];
                            sb += v0 * wbs[nf * 2] + v1 * wbs[nf * 2 + 1];
                            v0 *= QSCALE; v1 *= QSCALE;
                        }
                        const int t = n >> 2, b = n & 3, h = m >> 6, hd = m & 63;
                        *(half2*)&((__half*)C)[(((size_t)(b * H_DIM + h) * T_DIM) + t) * HD_DIM + hd] =
                            __floats2half2_rn(v0, v1);
                    } else { // E_GELU (exact) -> fp16
                        float g0 = 0.5f * v0 * (1.f + erff(v0 * 0.70710678118654752f));
                        float g1 = 0.5f * v1 * (1.f + erff(v1 * 0.70710678118654752f));
                        *(half2*)&((__half*)C)[(size_t)n * ldc + m] = __floats2half2_rn(g0, g1);
                    }
                }
            }
            if (EPI == E_QKV && sel == 0) {
                sa += __shfl_xor_sync(0xffffffffu, sa, 1);
                sa += __shfl_xor_sync(0xffffffffu, sa, 2);
                sb += __shfl_xor_sync(0xffffffffu, sb, 1);
                sb += __shfl_xor_sync(0xffffffffu, sb, 2);
                if (c == 0) {
                    float ga = 1.f / (1.f + __expf(-(sa + bsum_a)));
                    float gb = 1.f / (1.f + __expf(-(sb + bsum_b)));
                    const int t = n >> 2, b = n & 3, h = (m0 + wc) >> 6;
                    gate_out[(b * H_DIM + h) * T_DIM + t] = ga * (gb * gah - 1.f) + 2.f;
                }
            }
        }
    }
}

// ---------------------------------------------------------------------------
// Tensor-core flash attention + fused pb passthrough copy.
// 64 q-rows/CTA, 128 threads (4 warps x 16 rows) -> grid (16, 48) = 768 CTAs
// for better wave balance. Per-warp structure identical to R13 version.
// 3-stage KV ring -> ONE block barrier per tile; pb staged per-warp.
// smem: Q 64x72h | K 3x64x72h | V 3x64x72h | PB 64x72f | gates 64f
// ---------------------------------------------------------------------------
#define FA_QROWS 64
#define FA_QH   (FA_QROWS * 72)   // halves
#define FA_KVH  (64 * 72)         // halves per stage
#define FA_SMEM (FA_QH * 2 + 6 * FA_KVH * 2 + FA_QROWS * 72 * 4 + 512)

__global__ __launch_bounds__(128, 2) void flash_attn_h(
    const __half* __restrict__ q, const __half* __restrict__ k,
    const __half* __restrict__ v, const float* __restrict__ pb,
    const float* __restrict__ gate, __half* __restrict__ ctx,
    float* __restrict__ outpb)
{
    extern __shared__ __half smh[];
    __half* Qs  = smh;                        // 64x72 h
    __half* Ks  = smh + FA_QH;                // 3 stages 64x72 h
    __half* Vs  = smh + FA_QH + 3 * FA_KVH;   // 3 stages
    float*  PBs = (float*)(smh + FA_QH + 6 * FA_KVH);   // 64x72 f
    float*  Gs  = PBs + FA_QROWS * 72;

    const int bh   = blockIdx.y;
    const int q0   = blockIdx.x * FA_QROWS;
    const int tid  = threadIdx.x;
    const int lane = tid & 31;
    const int w    = tid >> 5;                // 0..3
    const int g    = lane >> 2;
    const int c    = lane & 3;

    const __half* qg = q + ((size_t)bh * T_DIM + q0) * 64;
    const __half* kg = k + (size_t)bh * 65536;
    const __half* vg = v + (size_t)bh * 65536;
    const float*  pbg = pb + ((size_t)bh * T_DIM + q0) * T_DIM;

    // group 1: Q + KV tile0 (stage 0) + pb tile0 ; group 2: KV tile1 (stage 1)
#pragma unroll
    for (int i = tid; i < 512; i += 128) {
        int row = i >> 3, ch = (i & 7) * 8;
        cp16(&Qs[row * 72 + ch], qg + row * 64 + ch);
        cp16(&Ks[row * 72 + ch], kg + row * 64 + ch);
        cp16(&Vs[row * 72 + ch], vg + row * 64 + ch);
    }
#pragma unroll
    for (int it = 0; it < 8; it++) {
        int cidx = lane + it * 32;               // 256 chunks per warp
        int row  = w * 16 + (cidx >> 4);
        int chf  = (cidx & 15) * 4;
        cp16(&PBs[row * 72 + chf], pbg + (size_t)row * T_DIM + chf);
    }
    CP_COMMIT();
#pragma unroll
    for (int i = tid; i < 512; i += 128) {
        int row = i >> 3, ch = (i & 7) * 8;
        cp16(&Ks[FA_KVH + row * 72 + ch], kg + 4096 + row * 64 + ch);
        cp16(&Vs[FA_KVH + row * 72 + ch], vg + 4096 + row * 64 + ch);
    }
    CP_COMMIT();
    if (tid < FA_QROWS) Gs[tid] = gate[bh * T_DIM + q0 + tid];

    CP_WAIT(1);
    __syncthreads();

    // Q fragments (persist in registers)
    unsigned af[4][4];
    {
        const int ar  = w * 16 + (lane & 15);
        const int akb = (lane >> 4) * 8;
#pragma unroll
        for (int ks = 0; ks < 4; ks++)
            ldsm_x4(af[ks], sm_u32(&Qs[ar * 72 + ks * 16 + akb]));
    }

    float m0 = -1e30f, m1 = -1e30f, l0 = 0.f, l1 = 0.f;
    float oacc[8][4];
#pragma unroll
    for (int hb = 0; hb < 8; hb++)
#pragma unroll
        for (int j = 0; j < 4; j++) oacc[hb][j] = 0.f;

    const float gr0 = Gs[w * 16 + g];
    const float gr1 = Gs[w * 16 + g + 8];
    float* opb0 = outpb + ((size_t)bh * T_DIM + q0 + w * 16 + g) * T_DIM;
    float* opb1 = opb0 + 8 * T_DIM;

    const int brow = (lane & 7) + ((lane >> 4) & 1) * 8;
    const int bkb  = ((lane >> 3) & 1) * 8;
    const int vr   = lane & 15;
    const int vcb  = (lane >> 4) * 8;
    const int prow0 = (w * 16 + g) * 72;

    for (int t = 0; t < 16; t++) {
        const int st = t % 3;
        // (1) KV(t) ready. outstanding allowed: {PB(t), KV(t+1)}  [t=15: {PB15}]
        if (t) {
            if (t < 15) CP_WAIT(2); else CP_WAIT(1);
            __syncthreads();
        }
        // (1b) early prefetch KV(t+2) into stage (t+2)%3 (freed by barrier above)
        if (t + 2 < 16) {
            const __half* ks2 = kg + (t + 2) * 4096;
            const __half* vs2 = vg + (t + 2) * 4096;
            __half* kd = Ks + ((t + 2) % 3) * FA_KVH;
            __half* vd = Vs + ((t + 2) % 3) * FA_KVH;
#pragma unroll
            for (int i = tid; i < 512; i += 128) {
                int row = i >> 3, ch = (i & 7) * 8;
                cp16(&kd[row * 72 + ch], ks2 + row * 64 + ch);
                cp16(&vd[row * 72 + ch], vs2 + row * 64 + ch);
            }
            CP_COMMIT();
        }
        const __half* Kb = Ks + st * FA_KVH;
        const __half* Vb = Vs + st * FA_KVH;

        // (2) S = Q @ K^T
        float sacc[8][4];
#pragma unroll
        for (int nb = 0; nb < 8; nb++)
#pragma unroll
            for (int j = 0; j < 4; j++) sacc[nb][j] = 0.f;

#pragma unroll
        for (int nb2 = 0; nb2 < 4; nb2++) {
#pragma unroll
            for (int ks = 0; ks < 4; ks++) {
                unsigned bf[4];
                ldsm_x4(bf, sm_u32(&Kb[(nb2 * 16 + brow) * 72 + ks * 16 + bkb]));
                mma_fp16(sacc[nb2 * 2],     af[ks], bf[0], bf[1]);
                mma_fp16(sacc[nb2 * 2 + 1], af[ks], bf[2], bf[3]);
            }
        }

        // (3) PB(t) ready (warp-local rows).
        if (t < 14) CP_WAIT(1); else CP_WAIT(0);
        __syncwarp();

        // (4) logits + passthrough + online softmax
        float mx0 = -1e30f, mx1 = -1e30f;
#pragma unroll
        for (int nb = 0; nb < 8; nb++) {
            float2 p0 = *(const float2*)&PBs[prow0 + nb * 8 + c * 2];
            float2 p1 = *(const float2*)&PBs[prow0 + 8 * 72 + nb * 8 + c * 2];
            *(float2*)&opb0[t * 64 + nb * 8 + c * 2] = p0;
            *(float2*)&opb1[t * 64 + nb * 8 + c * 2] = p1;
            sacc[nb][0] = 32.f * sacc[nb][0] + gr0 * p0.x;
            sacc[nb][1] = 32.f * sacc[nb][1] + gr0 * p0.y;
            sacc[nb][2] = 32.f * sacc[nb][2] + gr1 * p1.x;
            sacc[nb][3] = 32.f * sacc[nb][3] + gr1 * p1.y;
            mx0 = fmaxf(mx0, fmaxf(sacc[nb][0], sacc[nb][1]));
            mx1 = fmaxf(mx1, fmaxf(sacc[nb][2], sacc[nb][3]));
        }
        mx0 = fmaxf(mx0, __shfl_xor_sync(0xffffffffu, mx0, 1));
        mx0 = fmaxf(mx0, __shfl_xor_sync(0xffffffffu, mx0, 2));
        mx1 = fmaxf(mx1, __shfl_xor_sync(0xffffffffu, mx1, 1));
        mx1 = fmaxf(mx1, __shfl_xor_sync(0xffffffffu, mx1, 2));

        const float nm0 = fmaxf(m0, mx0), nm1 = fmaxf(m1, mx1);
        const float corr0 = __expf(m0 - nm0), corr1 = __expf(m1 - nm1);
        m0 = nm0; m1 = nm1;

        unsigned pa[4][4];
        float s0 = 0.f, s1 = 0.f;
#pragma unroll
        for (int nb = 0; nb < 8; nb++) {
            float e0 = __expf(sacc[nb][0] - nm0);
            float e1 = __expf(sacc[nb][1] - nm0);
            float e2 = __expf(sacc[nb][2] - nm1);
            float e3 = __expf(sacc[nb][3] - nm1);
            s0 += e0 + e1; s1 += e2 + e3;
            const int kp = nb >> 1, off = (nb & 1) * 2;
            half2 h0 = __floats2half2_rn(e0, e1);
            half2 h1 = __floats2half2_rn(e2, e3);
            pa[kp][off]     = *(unsigned*)&h0;
            pa[kp][off + 1] = *(unsigned*)&h1;
        }
        s0 += __shfl_xor_sync(0xffffffffu, s0, 1);
        s0 += __shfl_xor_sync(0xffffffffu, s0, 2);
        s1 += __shfl_xor_sync(0xffffffffu, s1, 1);
        s1 += __shfl_xor_sync(0xffffffffu, s1, 2);
        l0 = l0 * corr0 + s0;
        l1 = l1 * corr1 + s1;

#pragma unroll
        for (int hb = 0; hb < 8; hb++) {
            oacc[hb][0] *= corr0; oacc[hb][1] *= corr0;
            oacc[hb][2] *= corr1; oacc[hb][3] *= corr1;
        }

        // (5) warp done reading its PB rows -> warp-local prefetch of pb(t+1)
        __syncwarp();
        if (t + 1 < 16) {
#pragma unroll
            for (int it = 0; it < 8; it++) {
                int cidx = lane + it * 32;
                int row  = w * 16 + (cidx >> 4);
                int chf  = (cidx & 15) * 4;
                cp16(&PBs[row * 72 + chf],
                     pbg + (size_t)row * T_DIM + (t + 1) * 64 + chf);
            }
            CP_COMMIT();
        }

        // (6) out += P @ V   (V loaded transposed); no bottom barrier needed
#pragma unroll
        for (int kp = 0; kp < 4; kp++) {
#pragma unroll
            for (int hb2 = 0; hb2 < 4; hb2++) {
                unsigned bv[4];
                ldsm_x4_t(bv, sm_u32(&Vb[(kp * 16 + vr) * 72 + hb2 * 16 + vcb]));
                mma_fp16(oacc[hb2 * 2],     pa[kp], bv[0], bv[1]);
                mma_fp16(oacc[hb2 * 2 + 1], pa[kp], bv[2], bv[3]);
            }
        }
    }

    // write ctx (fp16, (T,B,D) layout) for Wo GEMM
    const float i0 = 1.f / l0, i1 = 1.f / l1;
    const int b = bh / H_DIM, hh = bh % H_DIM;
    const int t0g = q0 + w * 16 + g;
#pragma unroll
    for (int hb = 0; hb < 8; hb++) {
        const int col = hh * 64 + hb * 8 + c * 2;
        half2 o0 = __floats2half2_rn(oacc[hb][0] * i0, oacc[hb][1] * i0);
        half2 o1 = __floats2half2_rn(oacc[hb][2] * i1, oacc[hb][3] * i1);
        *(half2*)&ctx[(size_t)(t0g * B_DIM + b) * D_DIM + col]       = o0;
        *(half2*)&ctx[(size_t)((t0g + 8) * B_DIM + b) * D_DIM + col] = o1;
    }
}

// ---------------------------------------------------------------------------
// LayerNorm (optionally emits fp16 copy and/or y2pre = r*ALPHA + b2)
// ---------------------------------------------------------------------------
__global__ void layernorm_kernel(const float* __restrict__ in,
                                 const float* __restrict__ g,
                                 const float* __restrict__ b,
                                 float* __restrict__ out,
                                 __half* __restrict__ hout,
                                 const float* __restrict__ rb2,
                                 float* __restrict__ y2o)
{
    const int row = blockIdx.x, tid = threadIdx.x;
    const float* xr = in + (size_t)row * D_DIM;
    float v0 = xr[tid], v1 = xr[tid + 256], v2 = xr[tid + 512];
    float s  = v0 + v1 + v2;
    float sq = v0 * v0 + v1 * v1 + v2 * v2;
#pragma unroll
    for (int o = 16; o; o >>= 1) {
        s  += __shfl_xor_sync(0xffffffffu, s,  o);
        sq += __shfl_xor_sync(0xffffffffu, sq, o);
    }
    __shared__ float ss[8], sqs[8], stats[2];
    const int w = tid >> 5, lane = tid & 31;
    if (lane == 0) { ss[w] = s; sqs[w] = sq; }
    __syncthreads();
    if (tid == 0) {
        float S = 0.f, SQ = 0.f;
        for (int i = 0; i < 8; i++) { S += ss[i]; SQ += sqs[i]; }
        float mu  = S * (1.f / 768.f);
        float var = SQ * (1.f / 768.f) - mu * mu;
        stats[0] = mu;
        stats[1] = rsqrtf(var + 1e-5f);
    }
    __syncthreads();
    const float mu = stats[0], rstd = stats[1];
    float r0 = (v0 - mu) * rstd * g[tid]       + b[tid];
    float r1 = (v1 - mu) * rstd * g[tid + 256] + b[tid + 256];
    float r2 = (v2 - mu) * rstd * g[tid + 512] + b[tid + 512];
    float* orow = out + (size_t)row * D_DIM;
    orow[tid] = r0; orow[tid + 256] = r1; orow[tid + 512] = r2;
    if (hout) {
        __half* hrow = hout + (size_t)row * D_DIM;
        hrow[tid] = __float2half_rn(r0);
        hrow[tid + 256] = __float2half_rn(r1);
        hrow[tid + 512] = __float2half_rn(r2);
    }
    if (y2o) {   // prefill for FFN2 split-K: y2 = x*ALPHA + b2
        float* yr = y2o + (size_t)row * D_DIM;
        yr[tid]       = r0 * ALPHA_C + rb2[tid];
        yr[tid + 256] = r1 * ALPHA_C + rb2[tid + 256];
        yr[tid + 512] = r2 * ALPHA_C + rb2[tid + 512];
    }
}

// ---------------------------------------------------------------------------
// Launch
// ---------------------------------------------------------------------------
extern "C" void kernel_launch(void* const* d_in, const int* in_sizes, int n_in,
                              void* d_out, int out_size)
{
    const float* states = (const float*)d_in[0];
    const float* pb     = (const float*)d_in[1];
    const float* Wq = (const float*)d_in[2];   const float* bq = (const float*)d_in[3];
    const float* Wk = (const float*)d_in[4];   const float* bk = (const float*)d_in[5];
    const float* Wv = (const float*)d_in[6];   const float* bv = (const float*)d_in[7];
    const float* Wo = (const float*)d_in[8];   const float* bo = (const float*)d_in[9];
    const float* grep_w = (const float*)d_in[10];
    const float* grep_b = (const float*)d_in[11];
    const float* grep_a = (const float*)d_in[12];
    const float* ln1_g  = (const float*)d_in[13];
    const float* ln1_b  = (const float*)d_in[14];
    const float* W1 = (const float*)d_in[15];  const float* b1 = (const float*)d_in[16];
    const float* W2 = (const float*)d_in[17];  const float* b2 = (const float*)d_in[18];
    const float* ln2_g  = (const float*)d_in[19];
    const float* ln2_b  = (const float*)d_in[20];
    float* out = (float*)d_out;

    __half *hstates, *hWq, *hWk, *hWv, *hWo, *hW1, *hW2;
    __half *hq, *hk, *hv, *hctx, *hx, *hh;
    float  *gate, *y1, *x, *y2;
    cudaGetSymbolAddress((void**)&hstates, g_hstates);
    cudaGetSymbolAddress((void**)&hWq, g_hWq);
    cudaGetSymbolAddress((void**)&hWk, g_hWk);
    cudaGetSymbolAddress((void**)&hWv, g_hWv);
    cudaGetSymbolAddress((void**)&hWo, g_hWo);
    cudaGetSymbolAddress((void**)&hW1, g_hW1);
    cudaGetSymbolAddress((void**)&hW2, g_hW2);
    cudaGetSymbolAddress((void**)&hq,  g_hq);
    cudaGetSymbolAddress((void**)&hk,  g_hk);
    cudaGetSymbolAddress((void**)&hv,  g_hv);
    cudaGetSymbolAddress((void**)&hctx, g_hctx);
    cudaGetSymbolAddress((void**)&hx,  g_hx);
    cudaGetSymbolAddress((void**)&hh,  g_hh);
    cudaGetSymbolAddress((void**)&gate, g_gate);
    cudaGetSymbolAddress((void**)&y1,  g_y1);
    cudaGetSymbolAddress((void**)&x,   g_x);
    cudaGetSymbolAddress((void**)&y2,  g_y2);

    cudaFuncSetAttribute(mm_h<E_QKV>,    cudaFuncAttributeMaxDynamicSharedMemorySize, MM_SMEM);
    cudaFuncSetAttribute(mm_h<E_ATOMIC>, cudaFuncAttributeMaxDynamicSharedMemorySize, MM_SMEM);
    cudaFuncSetAttribute(mm_h<E_GELU>,   cudaFuncAttributeMaxDynamicSharedMemorySize, MM_SMEM);
    cudaFuncSetAttribute(flash_attn_h,   cudaFuncAttributeMaxDynamicSharedMemorySize, FA_SMEM);

    const dim3 blk(256);

    // fp32 -> fp16 for states + weights ; also prefills y1 = states*ALPHA + bo
    f2h_all<<<2496, blk>>>(states, Wq, Wk, Wv, Wo, W1, W2, bo, y1);

    // Fused QKV projections + gate computation (fp16 tensor cores)
    mm_h<E_QKV><<<dim3(18, 32, 1), blk, MM_SMEM>>>(
        hstates, hWq, hWk, hWv, bq, bk, bv, hq, hk, hv,
        grep_w, grep_b, grep_a, gate, D_DIM, 0);

    // tensor-core flash attention (+ fused pb passthrough into out)
    // 64-row Q tiles: 768 CTAs for better wave balance; no combine needed.
    flash_attn_h<<<dim3(T_DIM / FA_QROWS, NHEADS), dim3(128), FA_SMEM>>>(
        hq, hk, hv, pb, gate, hctx, out + (size_t)NROWS * D_DIM);

    // Wo projection: split-K3 atomic GEMM into prefilled y1 (576 blocks ~ 1.95
    // waves), then LN1 (+y2 prefill)
    mm_h<E_ATOMIC><<<dim3(6, 32, 3), blk, MM_SMEM>>>(
        hctx, hWo, nullptr, nullptr, nullptr, nullptr, nullptr,
        y1, nullptr, nullptr,
        nullptr, nullptr, nullptr, nullptr, D_DIM, D_DIM);
    layernorm_kernel<<<NROWS, blk>>>(y1, ln1_g, ln1_b, x, hx, b2, y2);

    // FFN
    mm_h<E_GELU><<<dim3(24, 32, 1), blk, MM_SMEM>>>(
        hx, hW1, nullptr, nullptr, b1, nullptr, nullptr,
        hh, nullptr, nullptr,
        nullptr, nullptr, nullptr, nullptr, D_DIM, FF_DIM);
    mm_h<E_ATOMIC><<<dim3(6, 32, 3), blk, MM_SMEM>>>(
        hh, hW2, nullptr, nullptr, nullptr, nullptr, nullptr,
        y2, nullptr, nullptr,
        nullptr, nullptr, nullptr, nullptr, FF_DIM, D_DIM);
    layernorm_kernel<<<NROWS, blk>>>(y2, ln2_g, ln2_b, out, nullptr, nullptr, nullptr);
}